// round 9
// baseline (speedup 1.0000x reference)
#include <cuda_runtime.h>
#include <cuda_fp16.h>
#include <math.h>
#include <stdint.h>

#define BB 8
#define CC 512
#define HS 1024
#define KP 144
#define NO 9
#define HW 196

// ---------------- scratch (device globals; zero-initialized) ---------------
__device__ __align__(16) __half g_x2 [BB * HW * 1024];     // [(b,hw)][1024] = [Xh, Xh]
__device__ __align__(16) __half g_w12[HS * 1024];          // [h][1024] = [Wh | Wl]
__device__ __align__(16) __half g_w22[HS * 1024];
__device__ __align__(16) __half g_cp2[BB * 320 * HS];      // [b][320][i]: hi 0..143, lo 160..303
__device__ __align__(16) __half g_sp2[NO * BB * 160 * HS]; // [o*8+b][160][j]: rows 144..159 zero
__device__ __align__(16) __half g_G3 [NO * BB * 160 * 480];// [o*8+b][k][480] = [Gh|Gh|Gl]
__device__ float g_scale[BB * NO * HS];                    // [b*NO+o][i] = 1/max(norm,eps)

// ---------------- asm helpers ----------------------------------------------
__device__ __forceinline__ uint32_t smem_u32(const void* p) {
    uint32_t a;
    asm("{ .reg .u64 t; cvta.to.shared.u64 t, %1; cvt.u32.u64 %0, t; }" : "=r"(a) : "l"(p));
    return a;
}
__device__ __forceinline__ void cp16(uint32_t s, const void* g) {
    asm volatile("cp.async.cg.shared.global [%0], [%1], 16;" :: "r"(s), "l"(g));
}
__device__ __forceinline__ void cpcommit() { asm volatile("cp.async.commit_group;" ::: "memory"); }
__device__ __forceinline__ void cpwait0() { asm volatile("cp.async.wait_group 0;" ::: "memory"); }
__device__ __forceinline__ void cpwait1() { asm volatile("cp.async.wait_group 1;" ::: "memory"); }

__device__ __forceinline__ void ldsm4(uint32_t* r, uint32_t a) {
    asm volatile("ldmatrix.sync.aligned.m8n8.x4.shared.b16 {%0,%1,%2,%3}, [%4];"
                 : "=r"(r[0]), "=r"(r[1]), "=r"(r[2]), "=r"(r[3]) : "r"(a));
}
__device__ __forceinline__ void ldsm4t(uint32_t* r, uint32_t a) {
    asm volatile("ldmatrix.sync.aligned.m8n8.x4.trans.shared.b16 {%0,%1,%2,%3}, [%4];"
                 : "=r"(r[0]), "=r"(r[1]), "=r"(r[2]), "=r"(r[3]) : "r"(a));
}
__device__ __forceinline__ void mma_f16(float* c, const uint32_t* a, const uint32_t* b) {
    asm volatile(
        "mma.sync.aligned.m16n8k16.row.col.f32.f16.f16.f32 "
        "{%0,%1,%2,%3},{%4,%5,%6,%7},{%8,%9},{%0,%1,%2,%3};"
        : "+f"(c[0]), "+f"(c[1]), "+f"(c[2]), "+f"(c[3])
        : "r"(a[0]), "r"(a[1]), "r"(a[2]), "r"(a[3]), "r"(b[0]), "r"(b[1]));
}

// ---------------- convert kernels ------------------------------------------
__global__ void conv_w2(const float* __restrict__ w1, const float* __restrict__ w2) {
    int i = blockIdx.x * 256 + threadIdx.x;
    const float* s = blockIdx.y ? w2 : w1;
    __half* d = blockIdx.y ? g_w22 : g_w12;
    int h = i >> 9, c = i & 511;
    float v = s[i];
    __half hv = __float2half_rn(v);
    __half lv = __float2half_rn(v - __half2float(hv));
    int base = h * 1024 + c;
    d[base] = hv; d[base + 512] = lv;
}

__global__ void conv_x2(const float* __restrict__ x) {
    __shared__ float t[32][33];
    int b = blockIdx.z, hw0 = blockIdx.y * 32, c0 = blockIdx.x * 32;
    for (int i = threadIdx.y; i < 32; i += 8) {
        int hw = hw0 + threadIdx.x;
        t[i][threadIdx.x] = (hw < HW) ? x[((size_t)b * CC + c0 + i) * HW + hw] : 0.f;
    }
    __syncthreads();
    for (int i = threadIdx.y; i < 32; i += 8) {
        int hw = hw0 + i, c = c0 + threadIdx.x;
        if (hw < HW) {
            __half hv = __float2half_rn(t[threadIdx.x][i]);
            size_t base = ((size_t)b * HW + hw) * 1024 + c;
            g_x2[base] = hv; g_x2[base + 512] = hv;
        }
    }
}

// ---------------- projection GEMM (fp16 2-term, K'=1024) --------------------
#define PROJ_SMEM 40960
__global__ void __launch_bounds__(256, 2) proj_kernel(const float* __restrict__ b1,
                                                      const float* __restrict__ b2) {
    extern __shared__ char smraw[];
    __shared__ int soff[128];
    __shared__ int doff[128];
    const uint32_t sb = smem_u32(smraw);
    const int tid = threadIdx.x, wid = tid >> 5, l = tid & 31;

    const int h0 = blockIdx.x * 128;
    const int r0 = blockIdx.y * 128;
    const int o = r0 / (BB * KP);
    const int rem0 = r0 - o * (BB * KP);
    const int dy = (o == NO) ? 0 : (o / 3 - 1);
    const int dx = (o == NO) ? 0 : (o % 3 - 1);

    if (tid < 128) {
        int rr = rem0 + tid;
        int b = rr / KP, k = rr - b * KP;
        int yy = 1 + k / 12 + dy, xx = 1 + k % 12 + dx;
        soff[tid] = (b * HW + yy * 14 + xx) * 1024;
        doff[tid] = (((o == NO) ? (b * 320) : ((o * BB + b) * 160)) + k) * 1024;
    }
    const __half* W = (o == NO) ? g_w12 : g_w22;
    const float* bias = (o == NO) ? b1 : b2;
    __syncthreads();

    const uint32_t Ab[2] = {sb, sb + 10240};
    const uint32_t Bb[2] = {sb + 20480, sb + 30720};

    const int Wm = (wid >> 1) * 32, Wn = (wid & 1) * 64;
    const int aRow = (l & 15), aKb = (l >> 4) * 16;
    const int bN = (l & 7) + (l >> 4) * 8, bKb = ((l >> 3) & 1) * 16;

    float acc[2][8][4] = {};

    {
        #pragma unroll
        for (int i = 0; i < 2; i++) {
            int c = tid + i * 256, row = c >> 2, kc = c & 3;
            cp16(Ab[0] + row * 80 + kc * 16, g_x2 + soff[row] + kc * 8);
        }
        #pragma unroll
        for (int i = 0; i < 2; i++) {
            int c = tid + i * 256, row = c >> 2, kc = c & 3;
            cp16(Bb[0] + row * 80 + kc * 16, W + (size_t)(h0 + row) * 1024 + kc * 8);
        }
        cpcommit();
    }

    for (int it = 0; it < 32; ++it) {
        const int buf = it & 1;
        if (it + 1 < 32) {
            const int c0 = (it + 1) * 32, nb = buf ^ 1;
            #pragma unroll
            for (int i = 0; i < 2; i++) {
                int c = tid + i * 256, row = c >> 2, kc = c & 3;
                cp16(Ab[nb] + row * 80 + kc * 16, g_x2 + soff[row] + c0 + kc * 8);
            }
            #pragma unroll
            for (int i = 0; i < 2; i++) {
                int c = tid + i * 256, row = c >> 2, kc = c & 3;
                cp16(Bb[nb] + row * 80 + kc * 16, W + (size_t)(h0 + row) * 1024 + c0 + kc * 8);
            }
            cpcommit();
            cpwait1();
        } else {
            cpwait0();
        }
        __syncthreads();
        #pragma unroll
        for (int s = 0; s < 2; s++) {
            uint32_t a[2][4], bb[4][4];
            #pragma unroll
            for (int t = 0; t < 2; t++)
                ldsm4(a[t], Ab[buf] + (Wm + t * 16 + aRow) * 80 + s * 32 + aKb);
            #pragma unroll
            for (int p = 0; p < 4; p++)
                ldsm4(bb[p], Bb[buf] + (Wn + p * 16 + bN) * 80 + s * 32 + bKb);
            #pragma unroll
            for (int mt = 0; mt < 2; mt++)
                #pragma unroll
                for (int nt = 0; nt < 8; nt++)
                    mma_f16(acc[mt][nt], a[mt], &bb[nt >> 1][(nt & 1) * 2]);
        }
        __syncthreads();
    }

    float* stage = (float*)smraw;
    for (int half = 0; half < 2; ++half) {
        __syncthreads();
        if ((wid >> 2) == half) {
            int rbase = Wm - half * 64;
            #pragma unroll
            for (int mt = 0; mt < 2; mt++)
                #pragma unroll
                for (int nt = 0; nt < 8; nt++) {
                    int row = rbase + mt * 16 + (l >> 2);
                    int col = Wn + nt * 8 + 2 * (l & 3);
                    stage[row * 132 + col]           = acc[mt][nt][0];
                    stage[row * 132 + col + 1]       = acc[mt][nt][1];
                    stage[(row + 8) * 132 + col]     = acc[mt][nt][2];
                    stage[(row + 8) * 132 + col + 1] = acc[mt][nt][3];
                }
        }
        __syncthreads();
        for (int idx = tid; idx < 8192; idx += 256) {
            int m = idx >> 7, h = idx & 127;
            float v = stage[m * 132 + h] + bias[h0 + h];
            __half hv = __float2half_rn(v);
            int dbase = doff[half * 64 + m] + h0 + h;
            if (o == NO) {
                __half lv = __float2half_rn(v - __half2float(hv));
                g_cp2[dbase] = hv;
                g_cp2[dbase + 160 * 1024] = lv;
            } else {
                g_sp2[dbase] = hv;
            }
        }
    }
}

// ---------------- gram: G = sp·sp^T per sp-pair s=o*8+b (M=160,N=192,K=1024)
#define GRAM_SMEM (192 * 144 * 2)
__global__ void __launch_bounds__(256, 1) gram_kernel() {
    extern __shared__ char smraw[];
    const uint32_t sb = smem_u32(smraw);
    const int tid = threadIdx.x, wid = tid >> 5, l = tid & 31;
    const int p = blockIdx.x;                         // sp-index o*8+b
    const __half* Bgp = g_sp2 + (size_t)p * 160 * 1024;

    const uint32_t Tb[2] = {sb, sb + 192 * 144};
    const int m0 = (wid >> 2) * 80, n0 = (wid & 3) * 48;

    float acc[5][6][4] = {};

    for (int idx = tid; idx < 1280; idx += 256) {
        int row = idx >> 3, kc = idx & 7;
        cp16(Tb[0] + row * 144 + kc * 16, Bgp + (size_t)row * 1024 + kc * 8);
    }
    cpcommit();

    for (int it = 0; it < 16; ++it) {
        const int buf = it & 1;
        if (it + 1 < 16) {
            const int k0 = (it + 1) * 64, nb = buf ^ 1;
            for (int idx = tid; idx < 1280; idx += 256) {
                int row = idx >> 3, kc = idx & 7;
                cp16(Tb[nb] + row * 144 + kc * 16, Bgp + (size_t)row * 1024 + k0 + kc * 8);
            }
            cpcommit();
            cpwait1();
        } else {
            cpwait0();
        }
        __syncthreads();
        #pragma unroll
        for (int s = 0; s < 4; s++) {
            uint32_t a[5][4], bb[3][4];
            #pragma unroll
            for (int t = 0; t < 5; t++)
                ldsm4(a[t], Tb[buf] + (m0 + t * 16 + (l & 15)) * 144 + s * 32 + (l >> 4) * 16);
            #pragma unroll
            for (int q = 0; q < 3; q++)
                ldsm4(bb[q], Tb[buf] + (n0 + q * 16 + (l & 7) + (l >> 4) * 8) * 144 +
                             s * 32 + ((l >> 3) & 1) * 16);
            #pragma unroll
            for (int mt = 0; mt < 5; mt++)
                #pragma unroll
                for (int nt = 0; nt < 6; nt++)
                    mma_f16(acc[mt][nt], a[mt], &bb[nt >> 1][(nt & 1) * 2]);
        }
        __syncthreads();
    }

    __half* G3p = g_G3 + (size_t)p * 160 * 480;
    #pragma unroll
    for (int mt = 0; mt < 5; mt++) {
        #pragma unroll
        for (int nt = 0; nt < 6; nt++) {
            #pragma unroll
            for (int c = 0; c < 4; c++) {
                int gm = m0 + mt * 16 + (l >> 2) + (c >> 1) * 8;
                int gn = n0 + nt * 8 + 2 * (l & 3) + (c & 1);
                if (gn < 160) {
                    float v = acc[mt][nt][c];
                    __half hv = __float2half_rn(v);
                    __half lv = __float2half_rn(v - __half2float(hv));
                    __half* r = G3p + (size_t)gm * 480 + gn;
                    r[0] = hv; r[160] = hv; r[320] = lv;
                }
            }
        }
    }
}

// ---------------- tmat: T = G3·[h;l;h], S_i = sum_k a_ki T_ki, scale -------
// blockIdx.y = sp-index s = o*8+b  ->  b = s&7, o = s>>3; scale at [b*NO+o]
#define TMAT_SMEM (2 * (160 * 80 + 32 * 272) + 512)
__global__ void __launch_bounds__(256, 1) tmat_kernel() {
    extern __shared__ char smraw[];
    const uint32_t sb = smem_u32(smraw);
    float* S = (float*)(smraw + 2 * (160 * 80 + 32 * 272));
    const int tid = threadIdx.x, wid = tid >> 5, l = tid & 31;
    const int i0 = blockIdx.x * 128;
    const int ps = blockIdx.y;                 // sp-index o*8+b
    const int b = ps & 7, o = ps >> 3;
    const int pout = b * NO + o;               // output pair index

    const __half* G3p = g_G3 + (size_t)ps * 160 * 480;
    const __half* cp2b = g_cp2 + (size_t)b * 320 * 1024;

    const uint32_t Ab[2] = {sb, sb + 160 * 80 + 32 * 272};
    const uint32_t Bb[2] = {sb + 160 * 80, sb + 2 * 160 * 80 + 32 * 272};

    if (tid < 128) S[tid] = 0.f;

    const int m0 = (wid >> 2) * 80, n0 = (wid & 3) * 32;
    float acc[5][4][4] = {};

    {
        for (int idx = tid; idx < 640; idx += 256) {
            int row = idx >> 2, kc = idx & 3;
            cp16(Ab[0] + row * 80 + kc * 16, G3p + (size_t)row * 480 + kc * 8);
        }
        for (int idx = tid; idx < 512; idx += 256) {
            int kr = idx >> 4, jc = idx & 15;
            cp16(Bb[0] + kr * 272 + jc * 16, cp2b + (size_t)kr * 1024 + i0 + jc * 8);
        }
        cpcommit();
    }

    for (int it = 0; it < 15; ++it) {
        const int buf = it & 1;
        if (it + 1 < 15) {
            const int k0 = (it + 1) * 32, nb = buf ^ 1;
            for (int idx = tid; idx < 640; idx += 256) {
                int row = idx >> 2, kc = idx & 3;
                cp16(Ab[nb] + row * 80 + kc * 16, G3p + (size_t)row * 480 + k0 + kc * 8);
            }
            for (int idx = tid; idx < 512; idx += 256) {
                int kr = idx >> 4, jc = idx & 15;
                int kk = k0 + kr;
                int srow = (kk < 320) ? kk : (kk - 320);
                cp16(Bb[nb] + kr * 272 + jc * 16, cp2b + (size_t)srow * 1024 + i0 + jc * 8);
            }
            cpcommit();
            cpwait1();
        } else {
            cpwait0();
        }
        __syncthreads();
        #pragma unroll
        for (int s = 0; s < 2; s++) {
            uint32_t a[5][4], bb[2][4];
            #pragma unroll
            for (int t = 0; t < 5; t++)
                ldsm4(a[t], Ab[buf] + (m0 + t * 16 + (l & 15)) * 80 + s * 32 + (l >> 4) * 16);
            #pragma unroll
            for (int q = 0; q < 2; q++)
                ldsm4t(bb[q], Bb[buf] + (s * 16 + (l & 7) + ((l >> 3) & 1) * 8) * 272 +
                              (n0 + q * 16 + (l >> 4) * 8) * 2);
            #pragma unroll
            for (int mt = 0; mt < 5; mt++)
                #pragma unroll
                for (int nt = 0; nt < 4; nt++)
                    mma_f16(acc[mt][nt], a[mt], &bb[nt >> 1][(nt & 1) * 2]);
        }
        __syncthreads();
    }

    #pragma unroll
    for (int nt = 0; nt < 4; nt++) {
        #pragma unroll
        for (int cc = 0; cc < 2; cc++) {
            int gn = n0 + nt * 8 + 2 * (l & 3) + cc;
            float s1 = 0.f, s2 = 0.f;
            #pragma unroll
            for (int mt = 0; mt < 5; mt++) {
                int r1 = m0 + mt * 16 + (l >> 2);
                int r2 = r1 + 8;
                float a1 = __half2float(cp2b[(size_t)r1 * 1024 + i0 + gn]) +
                           __half2float(cp2b[(size_t)(160 + r1) * 1024 + i0 + gn]);
                float a2 = __half2float(cp2b[(size_t)r2 * 1024 + i0 + gn]) +
                           __half2float(cp2b[(size_t)(160 + r2) * 1024 + i0 + gn]);
                s1 += a1 * acc[mt][nt][cc];
                s2 += a2 * acc[mt][nt][2 + cc];
            }
            atomicAdd(&S[gn], s1 + s2);
        }
    }
    __syncthreads();
    if (tid < 128) {
        float nrm = sqrtf(S[tid]);
        g_scale[(size_t)pout * HS + i0 + tid] = 1.0f / fmaxf(nrm, 1e-12f);
    }
}

// ---------------- cofe GEMM (fp16, scaled epilogue) -------------------------
#define COFE_SMEM 84992
__global__ void __launch_bounds__(256, 1) cofe_kernel(float* __restrict__ out) {
    extern __shared__ char smraw[];
    const uint32_t sb = smem_u32(smraw);
    const int tid = threadIdx.x, wid = tid >> 5, l = tid & 31;
    const int j0 = blockIdx.x * 128, i0 = blockIdx.y * 256;
    const int p = blockIdx.z, b = p / NO, o = p - b * NO;

    const __half* A0g = g_cp2 + (size_t)b * 320 * 1024 + i0;
    const __half* A1g = A0g + (size_t)160 * 1024;
    const __half* Bg  = g_sp2 + (size_t)(o * BB + b) * 160 * 1024 + j0;

    const uint32_t AB0[2] = {sb, sb + 42496};
    const uint32_t AB1[2] = {sb + 16896, sb + 42496 + 16896};
    const uint32_t BBF[2] = {sb + 33792, sb + 42496 + 33792};

    const int Wm = (wid >> 1) * 64, Wn = (wid & 1) * 64;
    const int aK = (l & 7) + (l >> 4) * 8, aI = ((l >> 3) & 1) * 8;
    const int bK = (l & 7) + ((l >> 3) & 1) * 8, bJ = (l >> 4) * 8;

    float acc[4][8][4] = {};

    {
        #pragma unroll
        for (int i = 0; i < 4; i++) {
            int c = tid + i * 256, k = c >> 5, ic = c & 31;
            cp16(AB0[0] + k * 528 + ic * 16, A0g + (size_t)k * 1024 + ic * 8);
            cp16(AB1[0] + k * 528 + ic * 16, A1g + (size_t)k * 1024 + ic * 8);
        }
        #pragma unroll
        for (int i = 0; i < 2; i++) {
            int c = tid + i * 256, k = c >> 4, jc = c & 15;
            cp16(BBF[0] + k * 272 + jc * 16, Bg + (size_t)k * 1024 + jc * 8);
        }
        cpcommit();
    }

    for (int it = 0; it < 5; ++it) {
        const int buf = it & 1;
        if (it + 1 < 5) {
            const int k0 = (it + 1) * 32, nb = buf ^ 1;
            #pragma unroll
            for (int i = 0; i < 4; i++) {
                int c = tid + i * 256, k = c >> 5, ic = c & 31;
                cp16(AB0[nb] + k * 528 + ic * 16, A0g + (size_t)(k0 + k) * 1024 + ic * 8);
                cp16(AB1[nb] + k * 528 + ic * 16, A1g + (size_t)(k0 + k) * 1024 + ic * 8);
            }
            #pragma unroll
            for (int i = 0; i < 2; i++) {
                int c = tid + i * 256, k = c >> 4, jc = c & 15;
                cp16(BBF[nb] + k * 272 + jc * 16, Bg + (size_t)(k0 + k) * 1024 + jc * 8);
            }
            cpcommit();
            cpwait1();
        } else {
            cpwait0();
        }
        __syncthreads();
        #pragma unroll
        for (int s = 0; s < 2; s++) {
            if (s == 1 && it == 4) break;   // rows 144..159 zero pad
            uint32_t bb[4][4];
            #pragma unroll
            for (int q = 0; q < 4; q++)
                ldsm4t(bb[q], BBF[buf] + (s * 16 + bK) * 272 + (Wn + q * 16 + bJ) * 2);
            #pragma unroll
            for (int half = 0; half < 2; half++) {
                uint32_t a[4][4];
                const uint32_t Abase = half ? AB1[buf] : AB0[buf];
                #pragma unroll
                for (int t = 0; t < 4; t++)
                    ldsm4t(a[t], Abase + (s * 16 + aK) * 528 + (Wm + t * 16 + aI) * 2);
                #pragma unroll
                for (int mt = 0; mt < 4; mt++)
                    #pragma unroll
                    for (int nt = 0; nt < 8; nt++)
                        mma_f16(acc[mt][nt], a[mt], &bb[nt >> 1][(nt & 1) * 2]);
            }
        }
        __syncthreads();
    }

    float* outp = out + (size_t)p * HS * HS;
    const float* scl = g_scale + (size_t)p * HS + i0;
    #pragma unroll
    for (int mt = 0; mt < 4; mt++) {
        int lr = Wm + mt * 16 + (l >> 2);
        int gi = i0 + lr;
        float s1 = scl[lr], s2 = scl[lr + 8];
        #pragma unroll
        for (int nt = 0; nt < 8; nt++) {
            int gj = j0 + Wn + nt * 8 + 2 * (l & 3);
            *reinterpret_cast<float2*>(outp + (size_t)gi * HS + gj) =
                make_float2(acc[mt][nt][0] * s1, acc[mt][nt][1] * s1);
            *reinterpret_cast<float2*>(outp + (size_t)(gi + 8) * HS + gj) =
                make_float2(acc[mt][nt][2] * s2, acc[mt][nt][3] * s2);
        }
    }
}

// ---------------------------------------------------------------------------
extern "C" void kernel_launch(void* const* d_in, const int* in_sizes, int n_in,
                              void* d_out, int out_size) {
    const float* x  = (const float*)d_in[0];
    const float* w1 = (const float*)d_in[1];
    const float* b1 = (const float*)d_in[2];
    const float* w2 = (const float*)d_in[3];
    const float* b2 = (const float*)d_in[4];
    float* out = (float*)d_out;

    cudaFuncSetAttribute(proj_kernel, cudaFuncAttributeMaxDynamicSharedMemorySize, PROJ_SMEM);
    cudaFuncSetAttribute(gram_kernel, cudaFuncAttributeMaxDynamicSharedMemorySize, GRAM_SMEM);
    cudaFuncSetAttribute(tmat_kernel, cudaFuncAttributeMaxDynamicSharedMemorySize, TMAT_SMEM);
    cudaFuncSetAttribute(cofe_kernel, cudaFuncAttributeMaxDynamicSharedMemorySize, COFE_SMEM);

    conv_w2<<<dim3((HS * CC) / 256, 2), 256>>>(w1, w2);
    conv_x2<<<dim3(CC / 32, (HW + 31) / 32, BB), dim3(32, 8)>>>(x);
    proj_kernel<<<dim3(HS / 128, (10 * BB * KP) / 128), 256, PROJ_SMEM>>>(b1, b2);
    gram_kernel<<<NO * BB, 256, GRAM_SMEM>>>();
    tmat_kernel<<<dim3(HS / 128, NO * BB), 256, TMAT_SMEM>>>();
    cofe_kernel<<<dim3(HS / 128, HS / 256, BB * NO), 256, COFE_SMEM>>>(out);
}

// round 10
// speedup vs baseline: 1.2325x; 1.2325x over previous
#include <cuda_runtime.h>
#include <cuda_fp16.h>
#include <math.h>
#include <stdint.h>

#define BB 8
#define CC 512
#define HS 1024
#define KP 144
#define NO 9
#define HW 196

// ---------------- scratch (device globals; zero-initialized) ---------------
__device__ __align__(16) __half g_x2 [BB * HW * 1024];     // [(b,hw)][1024] = [Xh, Xh]
__device__ __align__(16) __half g_w12[HS * 1024];          // [h][1024] = [Wh | Wl]
__device__ __align__(16) __half g_w22[HS * 1024];
__device__ __align__(16) __half g_cp2[BB * 160 * HS];      // [b][160][i]: rows 144..159 zero
__device__ __align__(16) __half g_sp2[NO * BB * 160 * HS]; // [o*8+b][160][j]: rows 144..159 zero

// ---------------- asm helpers ----------------------------------------------
__device__ __forceinline__ uint32_t smem_u32(const void* p) {
    uint32_t a;
    asm("{ .reg .u64 t; cvta.to.shared.u64 t, %1; cvt.u32.u64 %0, t; }" : "=r"(a) : "l"(p));
    return a;
}
__device__ __forceinline__ void cp16(uint32_t s, const void* g) {
    asm volatile("cp.async.cg.shared.global [%0], [%1], 16;" :: "r"(s), "l"(g));
}
__device__ __forceinline__ void cpcommit() { asm volatile("cp.async.commit_group;" ::: "memory"); }
__device__ __forceinline__ void cpwait0() { asm volatile("cp.async.wait_group 0;" ::: "memory"); }
__device__ __forceinline__ void cpwait1() { asm volatile("cp.async.wait_group 1;" ::: "memory"); }

__device__ __forceinline__ void ldsm4(uint32_t* r, uint32_t a) {
    asm volatile("ldmatrix.sync.aligned.m8n8.x4.shared.b16 {%0,%1,%2,%3}, [%4];"
                 : "=r"(r[0]), "=r"(r[1]), "=r"(r[2]), "=r"(r[3]) : "r"(a));
}
__device__ __forceinline__ void ldsm4t(uint32_t* r, uint32_t a) {
    asm volatile("ldmatrix.sync.aligned.m8n8.x4.trans.shared.b16 {%0,%1,%2,%3}, [%4];"
                 : "=r"(r[0]), "=r"(r[1]), "=r"(r[2]), "=r"(r[3]) : "r"(a));
}
__device__ __forceinline__ void mma_f16(float* c, const uint32_t* a, const uint32_t* b) {
    asm volatile(
        "mma.sync.aligned.m16n8k16.row.col.f32.f16.f16.f32 "
        "{%0,%1,%2,%3},{%4,%5,%6,%7},{%8,%9},{%0,%1,%2,%3};"
        : "+f"(c[0]), "+f"(c[1]), "+f"(c[2]), "+f"(c[3])
        : "r"(a[0]), "r"(a[1]), "r"(a[2]), "r"(a[3]), "r"(b[0]), "r"(b[1]));
}

// ---------------- convert kernels ------------------------------------------
__global__ void conv_w2(const float* __restrict__ w1, const float* __restrict__ w2) {
    int i = blockIdx.x * 256 + threadIdx.x;
    const float* s = blockIdx.y ? w2 : w1;
    __half* d = blockIdx.y ? g_w22 : g_w12;
    int h = i >> 9, c = i & 511;
    float v = s[i];
    __half hv = __float2half_rn(v);
    __half lv = __float2half_rn(v - __half2float(hv));
    int base = h * 1024 + c;
    d[base] = hv; d[base + 512] = lv;
}

__global__ void conv_x2(const float* __restrict__ x) {
    __shared__ float t[32][33];
    int b = blockIdx.z, hw0 = blockIdx.y * 32, c0 = blockIdx.x * 32;
    for (int i = threadIdx.y; i < 32; i += 8) {
        int hw = hw0 + threadIdx.x;
        t[i][threadIdx.x] = (hw < HW) ? x[((size_t)b * CC + c0 + i) * HW + hw] : 0.f;
    }
    __syncthreads();
    for (int i = threadIdx.y; i < 32; i += 8) {
        int hw = hw0 + i, c = c0 + threadIdx.x;
        if (hw < HW) {
            __half hv = __float2half_rn(t[threadIdx.x][i]);
            size_t base = ((size_t)b * HW + hw) * 1024 + c;
            g_x2[base] = hv; g_x2[base + 512] = hv;
        }
    }
}

// ---------------- projection GEMM (fp16 2-term, K'=1024) --------------------
#define PROJ_SMEM 40960
__global__ void __launch_bounds__(256, 2) proj_kernel(const float* __restrict__ b1,
                                                      const float* __restrict__ b2) {
    extern __shared__ char smraw[];
    __shared__ int soff[128];
    __shared__ int doff[128];
    const uint32_t sb = smem_u32(smraw);
    const int tid = threadIdx.x, wid = tid >> 5, l = tid & 31;

    const int h0 = blockIdx.x * 128;
    const int r0 = blockIdx.y * 128;
    const int o = r0 / (BB * KP);
    const int rem0 = r0 - o * (BB * KP);
    const int dy = (o == NO) ? 0 : (o / 3 - 1);
    const int dx = (o == NO) ? 0 : (o % 3 - 1);

    if (tid < 128) {
        int rr = rem0 + tid;
        int b = rr / KP, k = rr - b * KP;
        int yy = 1 + k / 12 + dy, xx = 1 + k % 12 + dx;
        soff[tid] = (b * HW + yy * 14 + xx) * 1024;
        doff[tid] = (((o == NO) ? b : (8 + (o * BB + b) - 8)) * 0 + // placeholder, fixed below
                     ((o == NO) ? b : (o * BB + b)) * 160 + k) * 1024;
    }
    const __half* W = (o == NO) ? g_w12 : g_w22;
    const float* bias = (o == NO) ? b1 : b2;
    __half* Dst = (o == NO) ? g_cp2 : g_sp2;
    __syncthreads();

    const uint32_t Ab[2] = {sb, sb + 10240};
    const uint32_t Bb[2] = {sb + 20480, sb + 30720};

    const int Wm = (wid >> 1) * 32, Wn = (wid & 1) * 64;
    const int aRow = (l & 15), aKb = (l >> 4) * 16;
    const int bN = (l & 7) + (l >> 4) * 8, bKb = ((l >> 3) & 1) * 16;

    float acc[2][8][4] = {};

    {
        #pragma unroll
        for (int i = 0; i < 2; i++) {
            int c = tid + i * 256, row = c >> 2, kc = c & 3;
            cp16(Ab[0] + row * 80 + kc * 16, g_x2 + soff[row] + kc * 8);
        }
        #pragma unroll
        for (int i = 0; i < 2; i++) {
            int c = tid + i * 256, row = c >> 2, kc = c & 3;
            cp16(Bb[0] + row * 80 + kc * 16, W + (size_t)(h0 + row) * 1024 + kc * 8);
        }
        cpcommit();
    }

    for (int it = 0; it < 32; ++it) {
        const int buf = it & 1;
        if (it + 1 < 32) {
            const int c0 = (it + 1) * 32, nb = buf ^ 1;
            #pragma unroll
            for (int i = 0; i < 2; i++) {
                int c = tid + i * 256, row = c >> 2, kc = c & 3;
                cp16(Ab[nb] + row * 80 + kc * 16, g_x2 + soff[row] + c0 + kc * 8);
            }
            #pragma unroll
            for (int i = 0; i < 2; i++) {
                int c = tid + i * 256, row = c >> 2, kc = c & 3;
                cp16(Bb[nb] + row * 80 + kc * 16, W + (size_t)(h0 + row) * 1024 + c0 + kc * 8);
            }
            cpcommit();
            cpwait1();
        } else {
            cpwait0();
        }
        __syncthreads();
        #pragma unroll
        for (int s = 0; s < 2; s++) {
            uint32_t a[2][4], bb[4][4];
            #pragma unroll
            for (int t = 0; t < 2; t++)
                ldsm4(a[t], Ab[buf] + (Wm + t * 16 + aRow) * 80 + s * 32 + aKb);
            #pragma unroll
            for (int p = 0; p < 4; p++)
                ldsm4(bb[p], Bb[buf] + (Wn + p * 16 + bN) * 80 + s * 32 + bKb);
            #pragma unroll
            for (int mt = 0; mt < 2; mt++)
                #pragma unroll
                for (int nt = 0; nt < 8; nt++)
                    mma_f16(acc[mt][nt], a[mt], &bb[nt >> 1][(nt & 1) * 2]);
        }
        __syncthreads();
    }

    float* stage = (float*)smraw;
    for (int half = 0; half < 2; ++half) {
        __syncthreads();
        if ((wid >> 2) == half) {
            int rbase = Wm - half * 64;
            #pragma unroll
            for (int mt = 0; mt < 2; mt++)
                #pragma unroll
                for (int nt = 0; nt < 8; nt++) {
                    int row = rbase + mt * 16 + (l >> 2);
                    int col = Wn + nt * 8 + 2 * (l & 3);
                    stage[row * 132 + col]           = acc[mt][nt][0];
                    stage[row * 132 + col + 1]       = acc[mt][nt][1];
                    stage[(row + 8) * 132 + col]     = acc[mt][nt][2];
                    stage[(row + 8) * 132 + col + 1] = acc[mt][nt][3];
                }
        }
        __syncthreads();
        for (int idx = tid; idx < 8192; idx += 256) {
            int m = idx >> 7, h = idx & 127;
            float v = stage[m * 132 + h] + bias[h0 + h];
            Dst[doff[half * 64 + m] + h0 + h] = __float2half_rn(v);
        }
    }
}

// ---------------- cofe GEMM (fp16 single-term, K=144) -----------------------
// C[i][j] = sum_k cph[k][i] * sph[k][j]; BM=256, BN=128, 5 k-tiles (last half)
// smem per buf: A [32][528B] + B [32][272B] = 25600; x2 = 51200
#define COFE_SMEM 51200
__global__ void __launch_bounds__(256, 1) cofe_kernel(float* __restrict__ out) {
    extern __shared__ char smraw[];
    const uint32_t sb = smem_u32(smraw);
    const int tid = threadIdx.x, wid = tid >> 5, l = tid & 31;
    const int j0 = blockIdx.x * 128, i0 = blockIdx.y * 256;
    const int p = blockIdx.z, b = p / NO, o = p - b * NO;

    const __half* Ag = g_cp2 + (size_t)b * 160 * 1024 + i0;
    const __half* Bg = g_sp2 + (size_t)(o * BB + b) * 160 * 1024 + j0;

    const uint32_t AB[2]  = {sb, sb + 25600};
    const uint32_t BBF[2] = {sb + 16896, sb + 25600 + 16896};

    const int Wm = (wid >> 1) * 64, Wn = (wid & 1) * 64;
    const int aK = (l & 7) + (l >> 4) * 8, aI = ((l >> 3) & 1) * 8;
    const int bK = (l & 7) + ((l >> 3) & 1) * 8, bJ = (l >> 4) * 8;

    float acc[4][8][4] = {};

    {
        #pragma unroll
        for (int i = 0; i < 4; i++) {
            int c = tid + i * 256, k = c >> 5, ic = c & 31;
            cp16(AB[0] + k * 528 + ic * 16, Ag + (size_t)k * 1024 + ic * 8);
        }
        #pragma unroll
        for (int i = 0; i < 2; i++) {
            int c = tid + i * 256, k = c >> 4, jc = c & 15;
            cp16(BBF[0] + k * 272 + jc * 16, Bg + (size_t)k * 1024 + jc * 8);
        }
        cpcommit();
    }

    for (int it = 0; it < 5; ++it) {
        const int buf = it & 1;
        if (it + 1 < 5) {
            const int k0 = (it + 1) * 32, nb = buf ^ 1;
            #pragma unroll
            for (int i = 0; i < 4; i++) {
                int c = tid + i * 256, k = c >> 5, ic = c & 31;
                cp16(AB[nb] + k * 528 + ic * 16, Ag + (size_t)(k0 + k) * 1024 + ic * 8);
            }
            #pragma unroll
            for (int i = 0; i < 2; i++) {
                int c = tid + i * 256, k = c >> 4, jc = c & 15;
                cp16(BBF[nb] + k * 272 + jc * 16, Bg + (size_t)(k0 + k) * 1024 + jc * 8);
            }
            cpcommit();
            cpwait1();
        } else {
            cpwait0();
        }
        __syncthreads();
        #pragma unroll
        for (int s = 0; s < 2; s++) {
            if (s == 1 && it == 4) break;   // rows 144..159 zero pad
            uint32_t a[4][4], bb[4][4];
            #pragma unroll
            for (int q = 0; q < 4; q++)
                ldsm4t(bb[q], BBF[buf] + (s * 16 + bK) * 272 + (Wn + q * 16 + bJ) * 2);
            #pragma unroll
            for (int t = 0; t < 4; t++)
                ldsm4t(a[t], AB[buf] + (s * 16 + aK) * 528 + (Wm + t * 16 + aI) * 2);
            #pragma unroll
            for (int mt = 0; mt < 4; mt++)
                #pragma unroll
                for (int nt = 0; nt < 8; nt++)
                    mma_f16(acc[mt][nt], a[mt], &bb[nt >> 1][(nt & 1) * 2]);
        }
        __syncthreads();
    }

    float* outp = out + (size_t)p * HS * HS;
    #pragma unroll
    for (int mt = 0; mt < 4; mt++) {
        int gi = i0 + Wm + mt * 16 + (l >> 2);
        #pragma unroll
        for (int nt = 0; nt < 8; nt++) {
            int gj = j0 + Wn + nt * 8 + 2 * (l & 3);
            *reinterpret_cast<float2*>(outp + (size_t)gi * HS + gj) =
                make_float2(acc[mt][nt][0], acc[mt][nt][1]);
            *reinterpret_cast<float2*>(outp + (size_t)(gi + 8) * HS + gj) =
                make_float2(acc[mt][nt][2], acc[mt][nt][3]);
        }
    }
}

// ---------------- row normalize --------------------------------------------
__global__ void norm_kernel(float* __restrict__ out) {
    __shared__ float ws[8];
    __shared__ float sc;
    const size_t row = blockIdx.x;
    float4* p = reinterpret_cast<float4*>(out + row * HS);
    float4 v = p[threadIdx.x];
    float s = v.x * v.x + v.y * v.y + v.z * v.z + v.w * v.w;
    #pragma unroll
    for (int off = 16; off > 0; off >>= 1)
        s += __shfl_xor_sync(0xffffffffu, s, off);
    if ((threadIdx.x & 31) == 0) ws[threadIdx.x >> 5] = s;
    __syncthreads();
    if (threadIdx.x == 0) {
        float t = 0.f;
        #pragma unroll
        for (int i = 0; i < 8; i++) t += ws[i];
        sc = 1.0f / fmaxf(sqrtf(t), 1e-12f);
    }
    __syncthreads();
    float scale = sc;
    v.x *= scale; v.y *= scale; v.z *= scale; v.w *= scale;
    p[threadIdx.x] = v;
}

// ---------------------------------------------------------------------------
extern "C" void kernel_launch(void* const* d_in, const int* in_sizes, int n_in,
                              void* d_out, int out_size) {
    const float* x  = (const float*)d_in[0];
    const float* w1 = (const float*)d_in[1];
    const float* b1 = (const float*)d_in[2];
    const float* w2 = (const float*)d_in[3];
    const float* b2 = (const float*)d_in[4];
    float* out = (float*)d_out;

    cudaFuncSetAttribute(proj_kernel, cudaFuncAttributeMaxDynamicSharedMemorySize, PROJ_SMEM);
    cudaFuncSetAttribute(cofe_kernel, cudaFuncAttributeMaxDynamicSharedMemorySize, COFE_SMEM);

    conv_w2<<<dim3((HS * CC) / 256, 2), 256>>>(w1, w2);
    conv_x2<<<dim3(CC / 32, (HW + 31) / 32, BB), dim3(32, 8)>>>(x);
    proj_kernel<<<dim3(HS / 128, (10 * BB * KP) / 128), 256, PROJ_SMEM>>>(b1, b2);
    cofe_kernel<<<dim3(HS / 128, HS / 256, BB * NO), 256, COFE_SMEM>>>(out);
    norm_kernel<<<BB * NO * HS, 256>>>(out);
}

// round 11
// speedup vs baseline: 1.4551x; 1.1806x over previous
#include <cuda_runtime.h>
#include <cuda_fp16.h>
#include <math.h>
#include <stdint.h>

#define BB 8
#define CC 512
#define HS 1024
#define KP 144
#define NO 9
#define HW 196

// ---------------- scratch (device globals; zero-initialized) ---------------
__device__ __align__(16) __half g_x2 [BB * HW * CC];       // [(b,hw)][512] fp16
__device__ __align__(16) __half g_w12[HS * CC];            // [h][512] fp16
__device__ __align__(16) __half g_w22[HS * CC];
__device__ __align__(16) __half g_cp2[BB * 160 * HS];      // [b][160][i]: rows 144..159 zero
__device__ __align__(16) __half g_sp2[NO * BB * 160 * HS]; // [o*8+b][160][j]: rows 144..159 zero

// ---------------- asm helpers ----------------------------------------------
__device__ __forceinline__ uint32_t smem_u32(const void* p) {
    uint32_t a;
    asm("{ .reg .u64 t; cvta.to.shared.u64 t, %1; cvt.u32.u64 %0, t; }" : "=r"(a) : "l"(p));
    return a;
}
__device__ __forceinline__ void cp16(uint32_t s, const void* g) {
    asm volatile("cp.async.cg.shared.global [%0], [%1], 16;" :: "r"(s), "l"(g));
}
__device__ __forceinline__ void cpcommit() { asm volatile("cp.async.commit_group;" ::: "memory"); }
__device__ __forceinline__ void cpwait0() { asm volatile("cp.async.wait_group 0;" ::: "memory"); }
__device__ __forceinline__ void cpwait1() { asm volatile("cp.async.wait_group 1;" ::: "memory"); }

__device__ __forceinline__ void ldsm4(uint32_t* r, uint32_t a) {
    asm volatile("ldmatrix.sync.aligned.m8n8.x4.shared.b16 {%0,%1,%2,%3}, [%4];"
                 : "=r"(r[0]), "=r"(r[1]), "=r"(r[2]), "=r"(r[3]) : "r"(a));
}
__device__ __forceinline__ void ldsm4t(uint32_t* r, uint32_t a) {
    asm volatile("ldmatrix.sync.aligned.m8n8.x4.trans.shared.b16 {%0,%1,%2,%3}, [%4];"
                 : "=r"(r[0]), "=r"(r[1]), "=r"(r[2]), "=r"(r[3]) : "r"(a));
}
__device__ __forceinline__ void mma_f16(float* c, const uint32_t* a, const uint32_t* b) {
    asm volatile(
        "mma.sync.aligned.m16n8k16.row.col.f32.f16.f16.f32 "
        "{%0,%1,%2,%3},{%4,%5,%6,%7},{%8,%9},{%0,%1,%2,%3};"
        : "+f"(c[0]), "+f"(c[1]), "+f"(c[2]), "+f"(c[3])
        : "r"(a[0]), "r"(a[1]), "r"(a[2]), "r"(a[3]), "r"(b[0]), "r"(b[1]));
}

// ---------------- convert kernels ------------------------------------------
__global__ void conv_w2(const float* __restrict__ w1, const float* __restrict__ w2) {
    int i = blockIdx.x * 256 + threadIdx.x;
    const float* s = blockIdx.y ? w2 : w1;
    __half* d = blockIdx.y ? g_w22 : g_w12;
    d[i] = __float2half_rn(s[i]);
}

__global__ void conv_x2(const float* __restrict__ x) {
    __shared__ float t[32][33];
    int b = blockIdx.z, hw0 = blockIdx.y * 32, c0 = blockIdx.x * 32;
    for (int i = threadIdx.y; i < 32; i += 8) {
        int hw = hw0 + threadIdx.x;
        t[i][threadIdx.x] = (hw < HW) ? x[((size_t)b * CC + c0 + i) * HW + hw] : 0.f;
    }
    __syncthreads();
    for (int i = threadIdx.y; i < 32; i += 8) {
        int hw = hw0 + i, c = c0 + threadIdx.x;
        if (hw < HW)
            g_x2[((size_t)b * HW + hw) * CC + c] = __float2half_rn(t[threadIdx.x][i]);
    }
}

// ---------------- projection GEMM (fp16 single-term, K=512) -----------------
#define PROJ_SMEM 40960
__global__ void __launch_bounds__(256, 2) proj_kernel(const float* __restrict__ b1,
                                                      const float* __restrict__ b2) {
    extern __shared__ char smraw[];
    __shared__ int soff[128];
    __shared__ int doff[128];
    const uint32_t sb = smem_u32(smraw);
    const int tid = threadIdx.x, wid = tid >> 5, l = tid & 31;

    const int h0 = blockIdx.x * 128;
    const int r0 = blockIdx.y * 128;
    const int o = r0 / (BB * KP);
    const int rem0 = r0 - o * (BB * KP);
    const int dy = (o == NO) ? 0 : (o / 3 - 1);
    const int dx = (o == NO) ? 0 : (o % 3 - 1);

    if (tid < 128) {
        int rr = rem0 + tid;
        int b = rr / KP, k = rr - b * KP;
        int yy = 1 + k / 12 + dy, xx = 1 + k % 12 + dx;
        soff[tid] = (b * HW + yy * 14 + xx) * CC;
        doff[tid] = (((o == NO) ? b : (o * BB + b)) * 160 + k) * 1024;
    }
    const __half* W = (o == NO) ? g_w12 : g_w22;
    const float* bias = (o == NO) ? b1 : b2;
    __half* Dst = (o == NO) ? g_cp2 : g_sp2;
    __syncthreads();

    const uint32_t Ab[2] = {sb, sb + 10240};
    const uint32_t Bb[2] = {sb + 20480, sb + 30720};

    const int Wm = (wid >> 1) * 32, Wn = (wid & 1) * 64;
    const int aRow = (l & 15), aKb = (l >> 4) * 16;
    const int bN = (l & 7) + (l >> 4) * 8, bKb = ((l >> 3) & 1) * 16;

    float acc[2][8][4] = {};

    {
        #pragma unroll
        for (int i = 0; i < 2; i++) {
            int c = tid + i * 256, row = c >> 2, kc = c & 3;
            cp16(Ab[0] + row * 80 + kc * 16, g_x2 + soff[row] + kc * 8);
        }
        #pragma unroll
        for (int i = 0; i < 2; i++) {
            int c = tid + i * 256, row = c >> 2, kc = c & 3;
            cp16(Bb[0] + row * 80 + kc * 16, W + (size_t)(h0 + row) * CC + kc * 8);
        }
        cpcommit();
    }

    for (int it = 0; it < 16; ++it) {
        const int buf = it & 1;
        if (it + 1 < 16) {
            const int c0 = (it + 1) * 32, nb = buf ^ 1;
            #pragma unroll
            for (int i = 0; i < 2; i++) {
                int c = tid + i * 256, row = c >> 2, kc = c & 3;
                cp16(Ab[nb] + row * 80 + kc * 16, g_x2 + soff[row] + c0 + kc * 8);
            }
            #pragma unroll
            for (int i = 0; i < 2; i++) {
                int c = tid + i * 256, row = c >> 2, kc = c & 3;
                cp16(Bb[nb] + row * 80 + kc * 16, W + (size_t)(h0 + row) * CC + c0 + kc * 8);
            }
            cpcommit();
            cpwait1();
        } else {
            cpwait0();
        }
        __syncthreads();
        #pragma unroll
        for (int s = 0; s < 2; s++) {
            uint32_t a[2][4], bb[4][4];
            #pragma unroll
            for (int t = 0; t < 2; t++)
                ldsm4(a[t], Ab[buf] + (Wm + t * 16 + aRow) * 80 + s * 32 + aKb);
            #pragma unroll
            for (int p = 0; p < 4; p++)
                ldsm4(bb[p], Bb[buf] + (Wn + p * 16 + bN) * 80 + s * 32 + bKb);
            #pragma unroll
            for (int mt = 0; mt < 2; mt++)
                #pragma unroll
                for (int nt = 0; nt < 8; nt++)
                    mma_f16(acc[mt][nt], a[mt], &bb[nt >> 1][(nt & 1) * 2]);
        }
        __syncthreads();
    }

    float* stage = (float*)smraw;
    for (int half = 0; half < 2; ++half) {
        __syncthreads();
        if ((wid >> 2) == half) {
            int rbase = Wm - half * 64;
            #pragma unroll
            for (int mt = 0; mt < 2; mt++)
                #pragma unroll
                for (int nt = 0; nt < 8; nt++) {
                    int row = rbase + mt * 16 + (l >> 2);
                    int col = Wn + nt * 8 + 2 * (l & 3);
                    stage[row * 132 + col]           = acc[mt][nt][0];
                    stage[row * 132 + col + 1]       = acc[mt][nt][1];
                    stage[(row + 8) * 132 + col]     = acc[mt][nt][2];
                    stage[(row + 8) * 132 + col + 1] = acc[mt][nt][3];
                }
        }
        __syncthreads();
        for (int idx = tid; idx < 8192; idx += 256) {
            int m = idx >> 7, h = idx & 127;
            float v = stage[m * 132 + h] + bias[h0 + h];
            Dst[doff[half * 64 + m] + h0 + h] = __float2half_rn(v);
        }
    }
}

// ---------------- cofe GEMM (fp16, K=144, BM=128 BN=128, occ 2) -------------
// smem per buf: A [32][272B] + B [32][272B] = 17408; x2 = 34816
#define COFE_SMEM 34816
__global__ void __launch_bounds__(128, 2) cofe_kernel(float* __restrict__ out) {
    extern __shared__ char smraw[];
    const uint32_t sb = smem_u32(smraw);
    const int tid = threadIdx.x, wid = tid >> 5, l = tid & 31;
    const int j0 = blockIdx.x * 128, i0 = blockIdx.y * 128;
    const int p = blockIdx.z, b = p / NO, o = p - b * NO;

    const __half* Ag = g_cp2 + (size_t)b * 160 * 1024 + i0;
    const __half* Bg = g_sp2 + (size_t)(o * BB + b) * 160 * 1024 + j0;

    const uint32_t AB[2]  = {sb, sb + 17408};
    const uint32_t BBF[2] = {sb + 8704, sb + 17408 + 8704};

    const int Wm = (wid >> 1) * 64, Wn = (wid & 1) * 64;
    const int aK = (l & 7) + (l >> 4) * 8, aI = ((l >> 3) & 1) * 8;
    const int bK = (l & 7) + ((l >> 3) & 1) * 8, bJ = (l >> 4) * 8;

    float acc[4][8][4] = {};

    {
        #pragma unroll
        for (int i = 0; i < 5; i++) {
            int c = tid + i * 128;
            if (c < 544) {
                int k = c / 17, jc = c % 17;
                if (jc < 16) cp16(AB[0] + k * 272 + jc * 16, Ag + (size_t)k * 1024 + jc * 8);
            }
        }
        #pragma unroll
        for (int i = 0; i < 5; i++) {
            int c = tid + i * 128;
            if (c < 544) {
                int k = c / 17, jc = c % 17;
                if (jc < 16) cp16(BBF[0] + k * 272 + jc * 16, Bg + (size_t)k * 1024 + jc * 8);
            }
        }
        cpcommit();
    }

    for (int it = 0; it < 5; ++it) {
        const int buf = it & 1;
        if (it + 1 < 5) {
            const int k0 = (it + 1) * 32, nb = buf ^ 1;
            #pragma unroll
            for (int i = 0; i < 5; i++) {
                int c = tid + i * 128;
                if (c < 544) {
                    int k = c / 17, jc = c % 17;
                    if (jc < 16)
                        cp16(AB[nb] + k * 272 + jc * 16, Ag + (size_t)(k0 + k) * 1024 + jc * 8);
                }
            }
            #pragma unroll
            for (int i = 0; i < 5; i++) {
                int c = tid + i * 128;
                if (c < 544) {
                    int k = c / 17, jc = c % 17;
                    if (jc < 16)
                        cp16(BBF[nb] + k * 272 + jc * 16, Bg + (size_t)(k0 + k) * 1024 + jc * 8);
                }
            }
            cpcommit();
            cpwait1();
        } else {
            cpwait0();
        }
        __syncthreads();
        #pragma unroll
        for (int s = 0; s < 2; s++) {
            if (s == 1 && it == 4) break;   // rows 144..159 zero pad
            uint32_t a[4][4], bb[4][4];
            #pragma unroll
            for (int q = 0; q < 4; q++)
                ldsm4t(bb[q], BBF[buf] + (s * 16 + bK) * 272 + (Wn + q * 16 + bJ) * 2);
            #pragma unroll
            for (int t = 0; t < 4; t++)
                ldsm4t(a[t], AB[buf] + (s * 16 + aK) * 272 + (Wm + t * 16 + aI) * 2);
            #pragma unroll
            for (int mt = 0; mt < 4; mt++)
                #pragma unroll
                for (int nt = 0; nt < 8; nt++)
                    mma_f16(acc[mt][nt], a[mt], &bb[nt >> 1][(nt & 1) * 2]);
        }
        __syncthreads();
    }

    float* outp = out + (size_t)p * HS * HS;
    #pragma unroll
    for (int mt = 0; mt < 4; mt++) {
        int gi = i0 + Wm + mt * 16 + (l >> 2);
        #pragma unroll
        for (int nt = 0; nt < 8; nt++) {
            int gj = j0 + Wn + nt * 8 + 2 * (l & 3);
            *reinterpret_cast<float2*>(outp + (size_t)gi * HS + gj) =
                make_float2(acc[mt][nt][0], acc[mt][nt][1]);
            *reinterpret_cast<float2*>(outp + (size_t)(gi + 8) * HS + gj) =
                make_float2(acc[mt][nt][2], acc[mt][nt][3]);
        }
    }
}

// ---------------- row normalize --------------------------------------------
__global__ void norm_kernel(float* __restrict__ out) {
    __shared__ float ws[8];
    __shared__ float sc;
    const size_t row = blockIdx.x;
    float4* p = reinterpret_cast<float4*>(out + row * HS);
    float4 v = p[threadIdx.x];
    float s = v.x * v.x + v.y * v.y + v.z * v.z + v.w * v.w;
    #pragma unroll
    for (int off = 16; off > 0; off >>= 1)
        s += __shfl_xor_sync(0xffffffffu, s, off);
    if ((threadIdx.x & 31) == 0) ws[threadIdx.x >> 5] = s;
    __syncthreads();
    if (threadIdx.x == 0) {
        float t = 0.f;
        #pragma unroll
        for (int i = 0; i < 8; i++) t += ws[i];
        sc = 1.0f / fmaxf(sqrtf(t), 1e-12f);
    }
    __syncthreads();
    float scale = sc;
    v.x *= scale; v.y *= scale; v.z *= scale; v.w *= scale;
    p[threadIdx.x] = v;
}

// ---------------------------------------------------------------------------
extern "C" void kernel_launch(void* const* d_in, const int* in_sizes, int n_in,
                              void* d_out, int out_size) {
    const float* x  = (const float*)d_in[0];
    const float* w1 = (const float*)d_in[1];
    const float* b1 = (const float*)d_in[2];
    const float* w2 = (const float*)d_in[3];
    const float* b2 = (const float*)d_in[4];
    float* out = (float*)d_out;

    cudaFuncSetAttribute(proj_kernel, cudaFuncAttributeMaxDynamicSharedMemorySize, PROJ_SMEM);
    cudaFuncSetAttribute(cofe_kernel, cudaFuncAttributeMaxDynamicSharedMemorySize, COFE_SMEM);

    conv_w2<<<dim3((HS * CC) / 256, 2), 256>>>(w1, w2);
    conv_x2<<<dim3(CC / 32, (HW + 31) / 32, BB), dim3(32, 8)>>>(x);
    proj_kernel<<<dim3(HS / 128, (10 * BB * KP) / 128), 256, PROJ_SMEM>>>(b1, b2);
    cofe_kernel<<<dim3(HS / 128, HS / 128, BB * NO), 128, COFE_SMEM>>>(out);
    norm_kernel<<<BB * NO * HS, 256>>>(out);
}

// round 13
// speedup vs baseline: 1.6263x; 1.1177x over previous
#include <cuda_runtime.h>
#include <cuda_fp16.h>
#include <math.h>
#include <stdint.h>

#define BB 8
#define CC 512
#define HS 1024
#define KP 144
#define NO 9
#define HW 196

// ---------------- scratch (device globals; zero-initialized) ---------------
__device__ __align__(16) __half g_x2 [BB * HW * CC];       // [(b,hw)][512] fp16
__device__ __align__(16) __half g_w12[HS * CC];            // [h][512] fp16
__device__ __align__(16) __half g_w22[HS * CC];
__device__ __align__(16) __half g_cp2[BB * 160 * HS];      // [b][160][i]: rows 144..159 zero
__device__ __align__(16) __half g_sp2[NO * BB * 160 * HS]; // [o*8+b][160][j]: rows 144..159 zero
__device__ __align__(16) __half g_G  [NO * BB * 160 * 160];// [o*8+b][m][n] fp16 Gram
__device__ float g_scale[BB * NO * HS];                    // [b*NO+o][i]

// ---------------- asm helpers ----------------------------------------------
__device__ __forceinline__ uint32_t smem_u32(const void* p) {
    uint32_t a;
    asm("{ .reg .u64 t; cvta.to.shared.u64 t, %1; cvt.u32.u64 %0, t; }" : "=r"(a) : "l"(p));
    return a;
}
__device__ __forceinline__ void cp16(uint32_t s, const void* g) {
    asm volatile("cp.async.cg.shared.global [%0], [%1], 16;" :: "r"(s), "l"(g));
}
__device__ __forceinline__ void cpcommit() { asm volatile("cp.async.commit_group;" ::: "memory"); }
__device__ __forceinline__ void cpwait0() { asm volatile("cp.async.wait_group 0;" ::: "memory"); }
__device__ __forceinline__ void cpwait1() { asm volatile("cp.async.wait_group 1;" ::: "memory"); }

__device__ __forceinline__ void ldsm4(uint32_t* r, uint32_t a) {
    asm volatile("ldmatrix.sync.aligned.m8n8.x4.shared.b16 {%0,%1,%2,%3}, [%4];"
                 : "=r"(r[0]), "=r"(r[1]), "=r"(r[2]), "=r"(r[3]) : "r"(a));
}
__device__ __forceinline__ void ldsm4t(uint32_t* r, uint32_t a) {
    asm volatile("ldmatrix.sync.aligned.m8n8.x4.trans.shared.b16 {%0,%1,%2,%3}, [%4];"
                 : "=r"(r[0]), "=r"(r[1]), "=r"(r[2]), "=r"(r[3]) : "r"(a));
}
__device__ __forceinline__ void mma_f16(float* c, const uint32_t* a, const uint32_t* b) {
    asm volatile(
        "mma.sync.aligned.m16n8k16.row.col.f32.f16.f16.f32 "
        "{%0,%1,%2,%3},{%4,%5,%6,%7},{%8,%9},{%0,%1,%2,%3};"
        : "+f"(c[0]), "+f"(c[1]), "+f"(c[2]), "+f"(c[3])
        : "r"(a[0]), "r"(a[1]), "r"(a[2]), "r"(a[3]), "r"(b[0]), "r"(b[1]));
}

// ---------------- convert kernels ------------------------------------------
__global__ void conv_w2(const float* __restrict__ w1, const float* __restrict__ w2) {
    int i = blockIdx.x * 256 + threadIdx.x;
    const float* s = blockIdx.y ? w2 : w1;
    __half* d = blockIdx.y ? g_w22 : g_w12;
    d[i] = __float2half_rn(s[i]);
}

__global__ void conv_x2(const float* __restrict__ x) {
    __shared__ float t[32][33];
    int b = blockIdx.z, hw0 = blockIdx.y * 32, c0 = blockIdx.x * 32;
    for (int i = threadIdx.y; i < 32; i += 8) {
        int hw = hw0 + threadIdx.x;
        t[i][threadIdx.x] = (hw < HW) ? x[((size_t)b * CC + c0 + i) * HW + hw] : 0.f;
    }
    __syncthreads();
    for (int i = threadIdx.y; i < 32; i += 8) {
        int hw = hw0 + i, c = c0 + threadIdx.x;
        if (hw < HW)
            g_x2[((size_t)b * HW + hw) * CC + c] = __float2half_rn(t[threadIdx.x][i]);
    }
}

// ---------------- projection GEMM (fp16 single-term, K=512) -----------------
#define PROJ_SMEM 40960
__global__ void __launch_bounds__(256, 2) proj_kernel(const float* __restrict__ b1,
                                                      const float* __restrict__ b2) {
    extern __shared__ char smraw[];
    __shared__ int soff[128];
    __shared__ int doff[128];
    const uint32_t sb = smem_u32(smraw);
    const int tid = threadIdx.x, wid = tid >> 5, l = tid & 31;

    const int h0 = blockIdx.x * 128;
    const int r0 = blockIdx.y * 128;
    const int o = r0 / (BB * KP);
    const int rem0 = r0 - o * (BB * KP);
    const int dy = (o == NO) ? 0 : (o / 3 - 1);
    const int dx = (o == NO) ? 0 : (o % 3 - 1);

    if (tid < 128) {
        int rr = rem0 + tid;
        int b = rr / KP, k = rr - b * KP;
        int yy = 1 + k / 12 + dy, xx = 1 + k % 12 + dx;
        soff[tid] = (b * HW + yy * 14 + xx) * CC;
        doff[tid] = (((o == NO) ? b : (o * BB + b)) * 160 + k) * 1024;
    }
    const __half* W = (o == NO) ? g_w12 : g_w22;
    const float* bias = (o == NO) ? b1 : b2;
    __half* Dst = (o == NO) ? g_cp2 : g_sp2;
    __syncthreads();

    const uint32_t Ab[2] = {sb, sb + 10240};
    const uint32_t Bb[2] = {sb + 20480, sb + 30720};

    const int Wm = (wid >> 1) * 32, Wn = (wid & 1) * 64;
    const int aRow = (l & 15), aKb = (l >> 4) * 16;
    const int bN = (l & 7) + (l >> 4) * 8, bKb = ((l >> 3) & 1) * 16;

    float acc[2][8][4] = {};

    {
        #pragma unroll
        for (int i = 0; i < 2; i++) {
            int c = tid + i * 256, row = c >> 2, kc = c & 3;
            cp16(Ab[0] + row * 80 + kc * 16, g_x2 + soff[row] + kc * 8);
        }
        #pragma unroll
        for (int i = 0; i < 2; i++) {
            int c = tid + i * 256, row = c >> 2, kc = c & 3;
            cp16(Bb[0] + row * 80 + kc * 16, W + (size_t)(h0 + row) * CC + kc * 8);
        }
        cpcommit();
    }

    for (int it = 0; it < 16; ++it) {
        const int buf = it & 1;
        if (it + 1 < 16) {
            const int c0 = (it + 1) * 32, nb = buf ^ 1;
            #pragma unroll
            for (int i = 0; i < 2; i++) {
                int c = tid + i * 256, row = c >> 2, kc = c & 3;
                cp16(Ab[nb] + row * 80 + kc * 16, g_x2 + soff[row] + c0 + kc * 8);
            }
            #pragma unroll
            for (int i = 0; i < 2; i++) {
                int c = tid + i * 256, row = c >> 2, kc = c & 3;
                cp16(Bb[nb] + row * 80 + kc * 16, W + (size_t)(h0 + row) * CC + c0 + kc * 8);
            }
            cpcommit();
            cpwait1();
        } else {
            cpwait0();
        }
        __syncthreads();
        #pragma unroll
        for (int s = 0; s < 2; s++) {
            uint32_t a[2][4], bb[4][4];
            #pragma unroll
            for (int t = 0; t < 2; t++)
                ldsm4(a[t], Ab[buf] + (Wm + t * 16 + aRow) * 80 + s * 32 + aKb);
            #pragma unroll
            for (int p = 0; p < 4; p++)
                ldsm4(bb[p], Bb[buf] + (Wn + p * 16 + bN) * 80 + s * 32 + bKb);
            #pragma unroll
            for (int mt = 0; mt < 2; mt++)
                #pragma unroll
                for (int nt = 0; nt < 8; nt++)
                    mma_f16(acc[mt][nt], a[mt], &bb[nt >> 1][(nt & 1) * 2]);
        }
        __syncthreads();
    }

    float* stage = (float*)smraw;
    for (int half = 0; half < 2; ++half) {
        __syncthreads();
        if ((wid >> 2) == half) {
            int rbase = Wm - half * 64;
            #pragma unroll
            for (int mt = 0; mt < 2; mt++)
                #pragma unroll
                for (int nt = 0; nt < 8; nt++) {
                    int row = rbase + mt * 16 + (l >> 2);
                    int col = Wn + nt * 8 + 2 * (l & 3);
                    stage[row * 132 + col]           = acc[mt][nt][0];
                    stage[row * 132 + col + 1]       = acc[mt][nt][1];
                    stage[(row + 8) * 132 + col]     = acc[mt][nt][2];
                    stage[(row + 8) * 132 + col + 1] = acc[mt][nt][3];
                }
        }
        __syncthreads();
        for (int idx = tid; idx < 8192; idx += 256) {
            int m = idx >> 7, h = idx & 127;
            float v = stage[m * 132 + h] + bias[h0 + h];
            Dst[doff[half * 64 + m] + h0 + h] = __float2half_rn(v);
        }
    }
}

// ---------------- gram: G = sp·sp^T per sp-pair (M=160,N=192,K=1024) -------
#define GRAM_SMEM (192 * 144 * 2)
__global__ void __launch_bounds__(256, 1) gram_kernel() {
    extern __shared__ char smraw[];
    const uint32_t sb = smem_u32(smraw);
    const int tid = threadIdx.x, wid = tid >> 5, l = tid & 31;
    const int p = blockIdx.x;                         // sp-index o*8+b
    const __half* Bgp = g_sp2 + (size_t)p * 160 * 1024;

    const uint32_t Tb[2] = {sb, sb + 192 * 144};
    const int m0 = (wid >> 2) * 80, n0 = (wid & 3) * 48;

    float acc[5][6][4] = {};

    for (int idx = tid; idx < 1280; idx += 256) {
        int row = idx >> 3, kc = idx & 7;
        cp16(Tb[0] + row * 144 + kc * 16, Bgp + (size_t)row * 1024 + kc * 8);
    }
    cpcommit();

    for (int it = 0; it < 16; ++it) {
        const int buf = it & 1;
        if (it + 1 < 16) {
            const int k0 = (it + 1) * 64, nb = buf ^ 1;
            for (int idx = tid; idx < 1280; idx += 256) {
                int row = idx >> 3, kc = idx & 7;
                cp16(Tb[nb] + row * 144 + kc * 16, Bgp + (size_t)row * 1024 + k0 + kc * 8);
            }
            cpcommit();
            cpwait1();
        } else {
            cpwait0();
        }
        __syncthreads();
        #pragma unroll
        for (int s = 0; s < 4; s++) {
            uint32_t a[5][4], bb[3][4];
            #pragma unroll
            for (int t = 0; t < 5; t++)
                ldsm4(a[t], Tb[buf] + (m0 + t * 16 + (l & 15)) * 144 + s * 32 + (l >> 4) * 16);
            #pragma unroll
            for (int q = 0; q < 3; q++)
                ldsm4(bb[q], Tb[buf] + (n0 + q * 16 + (l & 7) + (l >> 4) * 8) * 144 +
                             s * 32 + ((l >> 3) & 1) * 16);
            #pragma unroll
            for (int mt = 0; mt < 5; mt++)
                #pragma unroll
                for (int nt = 0; nt < 6; nt++)
                    mma_f16(acc[mt][nt], a[mt], &bb[nt >> 1][(nt & 1) * 2]);
        }
        __syncthreads();
    }

    __half* Gp = g_G + (size_t)p * 160 * 160;
    #pragma unroll
    for (int mt = 0; mt < 5; mt++) {
        #pragma unroll
        for (int nt = 0; nt < 6; nt++) {
            #pragma unroll
            for (int c = 0; c < 4; c++) {
                int gm = m0 + mt * 16 + (l >> 2) + (c >> 1) * 8;
                int gn = n0 + nt * 8 + 2 * (l & 3) + (c & 1);
                if (gn < 160)
                    Gp[(size_t)gm * 160 + gn] = __float2half_rn(acc[mt][nt][c]);
            }
        }
    }
}

// ---------------- tmat2: T = G·cp, S_i = sum_k cp[k,i]·T[k,i] --------------
// M=160 (k), N=128 (i), K=160 (k'); A=G [k'][k], B=cp2 [k'][i] (resident)
// smem: A 2x[32][336B]=21504, Bres [160][272B]=43520, S 512 -> 65536
#define TMAT_SMEM 66048
__global__ void __launch_bounds__(256, 1) tmat_kernel() {
    extern __shared__ char smraw[];
    const uint32_t sb = smem_u32(smraw);
    const int tid = threadIdx.x, wid = tid >> 5, l = tid & 31;
    const int i0 = blockIdx.x * 128;
    const int ps = blockIdx.y;                 // sp-index o*8+b
    const int b = ps & 7, o = ps >> 3;
    const int pout = b * NO + o;

    const __half* Gp = g_G + (size_t)ps * 160 * 160;
    const __half* cpb = g_cp2 + (size_t)b * 160 * 1024 + i0;

    const uint32_t AB[2] = {sb, sb + 10752};
    const uint32_t Bres = sb + 21504;
    float* S = (float*)(smraw + 65024);

    if (tid < 128) S[tid] = 0.f;

    const int Wm = (wid >> 2) * 80, Wn = (wid & 3) * 32;
    const int aK = (l & 7) + (l >> 4) * 8, aI = ((l >> 3) & 1) * 8;
    const int bK = (l & 7) + ((l >> 3) & 1) * 8, bJ = (l >> 4) * 8;

    float acc[5][4][4] = {};

    // prologue: chunk 0 (A tile rows k'=0..31 all 160 cols; B rows 0..31)
    {
        #pragma unroll
        for (int i = 0; i < 3; i++) {
            int c = tid + i * 256;
            if (c < 640) {
                int row = c / 20, col = c % 20;
                cp16(AB[0] + row * 336 + col * 16, Gp + (size_t)row * 160 + col * 8);
            }
        }
        #pragma unroll
        for (int i = 0; i < 2; i++) {
            int c = tid + i * 256, row = c >> 4, col = c & 15;
            cp16(Bres + row * 272 + col * 16, cpb + (size_t)row * 1024 + col * 8);
        }
        cpcommit();
    }

    for (int it = 0; it < 5; ++it) {
        const int buf = it & 1;
        if (it + 1 < 5) {
            const int k0 = (it + 1) * 32, nb = buf ^ 1;
            #pragma unroll
            for (int i = 0; i < 3; i++) {
                int c = tid + i * 256;
                if (c < 640) {
                    int row = c / 20, col = c % 20;
                    cp16(AB[nb] + row * 336 + col * 16,
                         Gp + (size_t)(k0 + row) * 160 + col * 8);
                }
            }
            #pragma unroll
            for (int i = 0; i < 2; i++) {
                int c = tid + i * 256, row = c >> 4, col = c & 15;
                cp16(Bres + (k0 + row) * 272 + col * 16,
                     cpb + (size_t)(k0 + row) * 1024 + col * 8);
            }
            cpcommit();
            cpwait1();
        } else {
            cpwait0();
        }
        __syncthreads();
        #pragma unroll
        for (int s = 0; s < 2; s++) {
            if (s == 1 && it == 4) break;   // G rows k'=144..159 are zero
            uint32_t a[5][4], bb[2][4];
            #pragma unroll
            for (int t = 0; t < 5; t++)
                ldsm4t(a[t], AB[buf] + (s * 16 + aK) * 336 + (Wm + t * 16 + aI) * 2);
            #pragma unroll
            for (int q = 0; q < 2; q++)
                ldsm4t(bb[q], Bres + (it * 32 + s * 16 + bK) * 272 + (Wn + q * 16 + bJ) * 2);
            #pragma unroll
            for (int mt = 0; mt < 5; mt++)
                #pragma unroll
                for (int nt = 0; nt < 4; nt++)
                    mma_f16(acc[mt][nt], a[mt], &bb[nt >> 1][(nt & 1) * 2]);
        }
        __syncthreads();
    }

    // S_i += T[k][i] * cp[k][i], cp read from resident B smem
    #pragma unroll
    for (int nt = 0; nt < 4; nt++) {
        #pragma unroll
        for (int cc = 0; cc < 2; cc++) {
            int gn = Wn + nt * 8 + 2 * (l & 3) + cc;
            float s = 0.f;
            #pragma unroll
            for (int mt = 0; mt < 5; mt++) {
                int gm1 = Wm + mt * 16 + (l >> 2);
                int gm2 = gm1 + 8;
                float a1 = __half2float(*(const __half*)(smraw + 21504 + gm1 * 272 + gn * 2));
                float a2 = __half2float(*(const __half*)(smraw + 21504 + gm2 * 272 + gn * 2));
                s += a1 * acc[mt][nt][cc] + a2 * acc[mt][nt][2 + cc];
            }
            atomicAdd(&S[gn], s);
        }
    }
    __syncthreads();
    if (tid < 128) {
        float nrm = sqrtf(S[tid]);
        g_scale[(size_t)pout * HS + i0 + tid] = 1.0f / fmaxf(nrm, 1e-12f);
    }
}

// ---------------- cofe GEMM (fp16, K=144, BM=128 BN=128, occ 2, scaled) -----
#define COFE_SMEM 34816
__global__ void __launch_bounds__(128, 2) cofe_kernel(float* __restrict__ out) {
    extern __shared__ char smraw[];
    const uint32_t sb = smem_u32(smraw);
    const int tid = threadIdx.x, wid = tid >> 5, l = tid & 31;
    const int j0 = blockIdx.x * 128, i0 = blockIdx.y * 128;
    const int p = blockIdx.z, b = p / NO, o = p - b * NO;

    const __half* Ag = g_cp2 + (size_t)b * 160 * 1024 + i0;
    const __half* Bg = g_sp2 + (size_t)(o * BB + b) * 160 * 1024 + j0;

    const uint32_t AB[2]  = {sb, sb + 17408};
    const uint32_t BBF[2] = {sb + 8704, sb + 17408 + 8704};

    const int Wm = (wid >> 1) * 64, Wn = (wid & 1) * 64;
    const int aK = (l & 7) + (l >> 4) * 8, aI = ((l >> 3) & 1) * 8;
    const int bK = (l & 7) + ((l >> 3) & 1) * 8, bJ = (l >> 4) * 8;

    float acc[4][8][4] = {};

    {
        #pragma unroll
        for (int i = 0; i < 5; i++) {
            int c = tid + i * 128;
            if (c < 544) {
                int k = c / 17, jc = c % 17;
                if (jc < 16) cp16(AB[0] + k * 272 + jc * 16, Ag + (size_t)k * 1024 + jc * 8);
            }
        }
        #pragma unroll
        for (int i = 0; i < 5; i++) {
            int c = tid + i * 128;
            if (c < 544) {
                int k = c / 17, jc = c % 17;
                if (jc < 16) cp16(BBF[0] + k * 272 + jc * 16, Bg + (size_t)k * 1024 + jc * 8);
            }
        }
        cpcommit();
    }

    for (int it = 0; it < 5; ++it) {
        const int buf = it & 1;
        if (it + 1 < 5) {
            const int k0 = (it + 1) * 32, nb = buf ^ 1;
            #pragma unroll
            for (int i = 0; i < 5; i++) {
                int c = tid + i * 128;
                if (c < 544) {
                    int k = c / 17, jc = c % 17;
                    if (jc < 16)
                        cp16(AB[nb] + k * 272 + jc * 16, Ag + (size_t)(k0 + k) * 1024 + jc * 8);
                }
            }
            #pragma unroll
            for (int i = 0; i < 5; i++) {
                int c = tid + i * 128;
                if (c < 544) {
                    int k = c / 17, jc = c % 17;
                    if (jc < 16)
                        cp16(BBF[nb] + k * 272 + jc * 16, Bg + (size_t)(k0 + k) * 1024 + jc * 8);
                }
            }
            cpcommit();
            cpwait1();
        } else {
            cpwait0();
        }
        __syncthreads();
        #pragma unroll
        for (int s = 0; s < 2; s++) {
            if (s == 1 && it == 4) break;   // rows 144..159 zero pad
            uint32_t a[4][4], bb[4][4];
            #pragma unroll
            for (int q = 0; q < 4; q++)
                ldsm4t(bb[q], BBF[buf] + (s * 16 + bK) * 272 + (Wn + q * 16 + bJ) * 2);
            #pragma unroll
            for (int t = 0; t < 4; t++)
                ldsm4t(a[t], AB[buf] + (s * 16 + aK) * 272 + (Wm + t * 16 + aI) * 2);
            #pragma unroll
            for (int mt = 0; mt < 4; mt++)
                #pragma unroll
                for (int nt = 0; nt < 8; nt++)
                    mma_f16(acc[mt][nt], a[mt], &bb[nt >> 1][(nt & 1) * 2]);
        }
        __syncthreads();
    }

    float* outp = out + (size_t)p * HS * HS;
    const float* scl = g_scale + (size_t)p * HS + i0;
    #pragma unroll
    for (int mt = 0; mt < 4; mt++) {
        int lr = Wm + mt * 16 + (l >> 2);
        int gi = i0 + lr;
        float s1 = scl[lr], s2 = scl[lr + 8];
        #pragma unroll
        for (int nt = 0; nt < 8; nt++) {
            int gj = j0 + Wn + nt * 8 + 2 * (l & 3);
            *reinterpret_cast<float2*>(outp + (size_t)gi * HS + gj) =
                make_float2(acc[mt][nt][0] * s1, acc[mt][nt][1] * s1);
            *reinterpret_cast<float2*>(outp + (size_t)(gi + 8) * HS + gj) =
                make_float2(acc[mt][nt][2] * s2, acc[mt][nt][3] * s2);
        }
    }
}

// ---------------------------------------------------------------------------
extern "C" void kernel_launch(void* const* d_in, const int* in_sizes, int n_in,
                              void* d_out, int out_size) {
    const float* x  = (const float*)d_in[0];
    const float* w1 = (const float*)d_in[1];
    const float* b1 = (const float*)d_in[2];
    const float* w2 = (const float*)d_in[3];
    const float* b2 = (const float*)d_in[4];
    float* out = (float*)d_out;

    cudaFuncSetAttribute(proj_kernel, cudaFuncAttributeMaxDynamicSharedMemorySize, PROJ_SMEM);
    cudaFuncSetAttribute(gram_kernel, cudaFuncAttributeMaxDynamicSharedMemorySize, GRAM_SMEM);
    cudaFuncSetAttribute(tmat_kernel, cudaFuncAttributeMaxDynamicSharedMemorySize, TMAT_SMEM);
    cudaFuncSetAttribute(cofe_kernel, cudaFuncAttributeMaxDynamicSharedMemorySize, COFE_SMEM);

    conv_w2<<<dim3((HS * CC) / 256, 2), 256>>>(w1, w2);
    conv_x2<<<dim3(CC / 32, (HW + 31) / 32, BB), dim3(32, 8)>>>(x);
    proj_kernel<<<dim3(HS / 128, (10 * BB * KP) / 128), 256, PROJ_SMEM>>>(b1, b2);
    gram_kernel<<<NO * BB, 256, GRAM_SMEM>>>();
    tmat_kernel<<<dim3(HS / 128, NO * BB), 256, TMAT_SMEM>>>();
    cofe_kernel<<<dim3(HS / 128, HS / 128, BB * NO), 128, COFE_SMEM>>>(out);
}

// round 14
// speedup vs baseline: 1.7596x; 1.0820x over previous
#include <cuda_runtime.h>
#include <cuda_fp16.h>
#include <math.h>
#include <stdint.h>

#define BB 8
#define CC 512
#define HS 1024
#define KP 144
#define NO 9
#define HW 196

// ---------------- scratch (device globals; zero-initialized) ---------------
__device__ __align__(16) __half g_x2 [BB * HW * CC];       // [(b,hw)][512] fp16
__device__ __align__(16) __half g_w12[HS * CC];            // [h][512] fp16
__device__ __align__(16) __half g_w22[HS * CC];
__device__ __align__(16) __half g_cp2[BB * 160 * HS];      // [b][160][i]: rows 144..159 zero
__device__ __align__(16) __half g_sp2[NO * BB * 160 * HS]; // [o*8+b][160][j]: rows 144..159 zero
__device__ __align__(16) float  g_Gpart[2 * NO * BB * 160 * 160]; // fp32 K-split partials
__device__ __align__(16) __half g_G  [NO * BB * 160 * 160];// [o*8+b][m][n] fp16 Gram
__device__ float g_scale[BB * NO * HS];                    // [b*NO+o][i]

// ---------------- asm helpers ----------------------------------------------
__device__ __forceinline__ uint32_t smem_u32(const void* p) {
    uint32_t a;
    asm("{ .reg .u64 t; cvta.to.shared.u64 t, %1; cvt.u32.u64 %0, t; }" : "=r"(a) : "l"(p));
    return a;
}
__device__ __forceinline__ void cp16(uint32_t s, const void* g) {
    asm volatile("cp.async.cg.shared.global [%0], [%1], 16;" :: "r"(s), "l"(g));
}
__device__ __forceinline__ void cpcommit() { asm volatile("cp.async.commit_group;" ::: "memory"); }
__device__ __forceinline__ void cpwait0() { asm volatile("cp.async.wait_group 0;" ::: "memory"); }
__device__ __forceinline__ void cpwait1() { asm volatile("cp.async.wait_group 1;" ::: "memory"); }

__device__ __forceinline__ void ldsm4(uint32_t* r, uint32_t a) {
    asm volatile("ldmatrix.sync.aligned.m8n8.x4.shared.b16 {%0,%1,%2,%3}, [%4];"
                 : "=r"(r[0]), "=r"(r[1]), "=r"(r[2]), "=r"(r[3]) : "r"(a));
}
__device__ __forceinline__ void ldsm4t(uint32_t* r, uint32_t a) {
    asm volatile("ldmatrix.sync.aligned.m8n8.x4.trans.shared.b16 {%0,%1,%2,%3}, [%4];"
                 : "=r"(r[0]), "=r"(r[1]), "=r"(r[2]), "=r"(r[3]) : "r"(a));
}
__device__ __forceinline__ void mma_f16(float* c, const uint32_t* a, const uint32_t* b) {
    asm volatile(
        "mma.sync.aligned.m16n8k16.row.col.f32.f16.f16.f32 "
        "{%0,%1,%2,%3},{%4,%5,%6,%7},{%8,%9},{%0,%1,%2,%3};"
        : "+f"(c[0]), "+f"(c[1]), "+f"(c[2]), "+f"(c[3])
        : "r"(a[0]), "r"(a[1]), "r"(a[2]), "r"(a[3]), "r"(b[0]), "r"(b[1]));
}

// ---------------- convert kernels ------------------------------------------
__global__ void conv_w2(const float* __restrict__ w1, const float* __restrict__ w2) {
    int i = blockIdx.x * 256 + threadIdx.x;
    const float* s = blockIdx.y ? w2 : w1;
    __half* d = blockIdx.y ? g_w22 : g_w12;
    d[i] = __float2half_rn(s[i]);
}

__global__ void conv_x2(const float* __restrict__ x) {
    __shared__ float t[32][33];
    int b = blockIdx.z, hw0 = blockIdx.y * 32, c0 = blockIdx.x * 32;
    for (int i = threadIdx.y; i < 32; i += 8) {
        int hw = hw0 + threadIdx.x;
        t[i][threadIdx.x] = (hw < HW) ? x[((size_t)b * CC + c0 + i) * HW + hw] : 0.f;
    }
    __syncthreads();
    for (int i = threadIdx.y; i < 32; i += 8) {
        int hw = hw0 + i, c = c0 + threadIdx.x;
        if (hw < HW)
            g_x2[((size_t)b * HW + hw) * CC + c] = __float2half_rn(t[threadIdx.x][i]);
    }
}

// ---------------- projection GEMM (fp16 single-term, K=512) -----------------
#define PROJ_SMEM 40960
__global__ void __launch_bounds__(256, 2) proj_kernel(const float* __restrict__ b1,
                                                      const float* __restrict__ b2) {
    extern __shared__ char smraw[];
    __shared__ int soff[128];
    __shared__ int doff[128];
    const uint32_t sb = smem_u32(smraw);
    const int tid = threadIdx.x, wid = tid >> 5, l = tid & 31;

    const int h0 = blockIdx.x * 128;
    const int r0 = blockIdx.y * 128;
    const int o = r0 / (BB * KP);
    const int rem0 = r0 - o * (BB * KP);
    const int dy = (o == NO) ? 0 : (o / 3 - 1);
    const int dx = (o == NO) ? 0 : (o % 3 - 1);

    if (tid < 128) {
        int rr = rem0 + tid;
        int b = rr / KP, k = rr - b * KP;
        int yy = 1 + k / 12 + dy, xx = 1 + k % 12 + dx;
        soff[tid] = (b * HW + yy * 14 + xx) * CC;
        doff[tid] = (((o == NO) ? b : (o * BB + b)) * 160 + k) * 1024;
    }
    const __half* W = (o == NO) ? g_w12 : g_w22;
    const float* bias = (o == NO) ? b1 : b2;
    __half* Dst = (o == NO) ? g_cp2 : g_sp2;
    __syncthreads();

    const uint32_t Ab[2] = {sb, sb + 10240};
    const uint32_t Bb[2] = {sb + 20480, sb + 30720};

    const int Wm = (wid >> 1) * 32, Wn = (wid & 1) * 64;
    const int aRow = (l & 15), aKb = (l >> 4) * 16;
    const int bN = (l & 7) + (l >> 4) * 8, bKb = ((l >> 3) & 1) * 16;

    float acc[2][8][4] = {};

    {
        #pragma unroll
        for (int i = 0; i < 2; i++) {
            int c = tid + i * 256, row = c >> 2, kc = c & 3;
            cp16(Ab[0] + row * 80 + kc * 16, g_x2 + soff[row] + kc * 8);
        }
        #pragma unroll
        for (int i = 0; i < 2; i++) {
            int c = tid + i * 256, row = c >> 2, kc = c & 3;
            cp16(Bb[0] + row * 80 + kc * 16, W + (size_t)(h0 + row) * CC + kc * 8);
        }
        cpcommit();
    }

    for (int it = 0; it < 16; ++it) {
        const int buf = it & 1;
        if (it + 1 < 16) {
            const int c0 = (it + 1) * 32, nb = buf ^ 1;
            #pragma unroll
            for (int i = 0; i < 2; i++) {
                int c = tid + i * 256, row = c >> 2, kc = c & 3;
                cp16(Ab[nb] + row * 80 + kc * 16, g_x2 + soff[row] + c0 + kc * 8);
            }
            #pragma unroll
            for (int i = 0; i < 2; i++) {
                int c = tid + i * 256, row = c >> 2, kc = c & 3;
                cp16(Bb[nb] + row * 80 + kc * 16, W + (size_t)(h0 + row) * CC + c0 + kc * 8);
            }
            cpcommit();
            cpwait1();
        } else {
            cpwait0();
        }
        __syncthreads();
        #pragma unroll
        for (int s = 0; s < 2; s++) {
            uint32_t a[2][4], bb[4][4];
            #pragma unroll
            for (int t = 0; t < 2; t++)
                ldsm4(a[t], Ab[buf] + (Wm + t * 16 + aRow) * 80 + s * 32 + aKb);
            #pragma unroll
            for (int p = 0; p < 4; p++)
                ldsm4(bb[p], Bb[buf] + (Wn + p * 16 + bN) * 80 + s * 32 + bKb);
            #pragma unroll
            for (int mt = 0; mt < 2; mt++)
                #pragma unroll
                for (int nt = 0; nt < 8; nt++)
                    mma_f16(acc[mt][nt], a[mt], &bb[nt >> 1][(nt & 1) * 2]);
        }
        __syncthreads();
    }

    float* stage = (float*)smraw;
    for (int half = 0; half < 2; ++half) {
        __syncthreads();
        if ((wid >> 2) == half) {
            int rbase = Wm - half * 64;
            #pragma unroll
            for (int mt = 0; mt < 2; mt++)
                #pragma unroll
                for (int nt = 0; nt < 8; nt++) {
                    int row = rbase + mt * 16 + (l >> 2);
                    int col = Wn + nt * 8 + 2 * (l & 3);
                    stage[row * 132 + col]           = acc[mt][nt][0];
                    stage[row * 132 + col + 1]       = acc[mt][nt][1];
                    stage[(row + 8) * 132 + col]     = acc[mt][nt][2];
                    stage[(row + 8) * 132 + col + 1] = acc[mt][nt][3];
                }
        }
        __syncthreads();
        for (int idx = tid; idx < 8192; idx += 256) {
            int m = idx >> 7, h = idx & 127;
            float v = stage[m * 132 + h] + bias[h0 + h];
            Dst[doff[half * 64 + m] + h0 + h] = __float2half_rn(v);
        }
    }
}

// ---------------- gram: split-K partials. blockIdx.x = p*2+half ------------
// Each CTA: G_part = sp[:, half*512 : +512]·spᵀ, M=160, N=192, K=512 (fp32 out)
#define GRAM_SMEM (192 * 144 * 2)
__global__ void __launch_bounds__(256, 1) gram_kernel() {
    extern __shared__ char smraw[];
    const uint32_t sb = smem_u32(smraw);
    const int tid = threadIdx.x, wid = tid >> 5, l = tid & 31;
    const int p = blockIdx.x >> 1, half = blockIdx.x & 1;
    const __half* Bgp = g_sp2 + (size_t)p * 160 * 1024 + half * 512;

    const uint32_t Tb[2] = {sb, sb + 192 * 144};
    const int m0 = (wid >> 2) * 80, n0 = (wid & 3) * 48;

    float acc[5][6][4] = {};

    for (int idx = tid; idx < 1280; idx += 256) {
        int row = idx >> 3, kc = idx & 7;
        cp16(Tb[0] + row * 144 + kc * 16, Bgp + (size_t)row * 1024 + kc * 8);
    }
    cpcommit();

    for (int it = 0; it < 8; ++it) {
        const int buf = it & 1;
        if (it + 1 < 8) {
            const int k0 = (it + 1) * 64, nb = buf ^ 1;
            for (int idx = tid; idx < 1280; idx += 256) {
                int row = idx >> 3, kc = idx & 7;
                cp16(Tb[nb] + row * 144 + kc * 16, Bgp + (size_t)row * 1024 + k0 + kc * 8);
            }
            cpcommit();
            cpwait1();
        } else {
            cpwait0();
        }
        __syncthreads();
        #pragma unroll
        for (int s = 0; s < 4; s++) {
            uint32_t a[5][4], bb[3][4];
            #pragma unroll
            for (int t = 0; t < 5; t++)
                ldsm4(a[t], Tb[buf] + (m0 + t * 16 + (l & 15)) * 144 + s * 32 + (l >> 4) * 16);
            #pragma unroll
            for (int q = 0; q < 3; q++)
                ldsm4(bb[q], Tb[buf] + (n0 + q * 16 + (l & 7) + (l >> 4) * 8) * 144 +
                             s * 32 + ((l >> 3) & 1) * 16);
            #pragma unroll
            for (int mt = 0; mt < 5; mt++)
                #pragma unroll
                for (int nt = 0; nt < 6; nt++)
                    mma_f16(acc[mt][nt], a[mt], &bb[nt >> 1][(nt & 1) * 2]);
        }
        __syncthreads();
    }

    float* Gp = g_Gpart + (size_t)blockIdx.x * 25600;
    #pragma unroll
    for (int mt = 0; mt < 5; mt++) {
        #pragma unroll
        for (int nt = 0; nt < 6; nt++) {
            #pragma unroll
            for (int c = 0; c < 4; c++) {
                int gm = m0 + mt * 16 + (l >> 2) + (c >> 1) * 8;
                int gn = n0 + nt * 8 + 2 * (l & 3) + (c & 1);
                if (gn < 160)
                    Gp[(size_t)gm * 160 + gn] = acc[mt][nt][c];
            }
        }
    }
}

// ---------------- greduce: G = fp16(part0 + part1) --------------------------
__global__ void greduce_kernel() {
    int idx = blockIdx.x * 256 + threadIdx.x;         // over 72*25600
    int p = idx / 25600;
    size_t srcbase = (size_t)idx + (size_t)p * 25600;
    g_G[idx] = __float2half_rn(g_Gpart[srcbase] + g_Gpart[srcbase + 25600]);
}

// ---------------- tmat2: T = G·cp, S_i = sum_k cp[k,i]·T[k,i] --------------
#define TMAT_SMEM 66048
__global__ void __launch_bounds__(256, 1) tmat_kernel() {
    extern __shared__ char smraw[];
    const uint32_t sb = smem_u32(smraw);
    const int tid = threadIdx.x, wid = tid >> 5, l = tid & 31;
    const int i0 = blockIdx.x * 128;
    const int ps = blockIdx.y;                 // sp-index o*8+b
    const int b = ps & 7, o = ps >> 3;
    const int pout = b * NO + o;

    const __half* Gp = g_G + (size_t)ps * 160 * 160;
    const __half* cpb = g_cp2 + (size_t)b * 160 * 1024 + i0;

    const uint32_t AB[2] = {sb, sb + 10752};
    const uint32_t Bres = sb + 21504;
    float* S = (float*)(smraw + 65024);

    if (tid < 128) S[tid] = 0.f;

    const int Wm = (wid >> 2) * 80, Wn = (wid & 3) * 32;
    const int aK = (l & 7) + (l >> 4) * 8, aI = ((l >> 3) & 1) * 8;
    const int bK = (l & 7) + ((l >> 3) & 1) * 8, bJ = (l >> 4) * 8;

    float acc[5][4][4] = {};

    {
        #pragma unroll
        for (int i = 0; i < 3; i++) {
            int c = tid + i * 256;
            if (c < 640) {
                int row = c / 20, col = c % 20;
                cp16(AB[0] + row * 336 + col * 16, Gp + (size_t)row * 160 + col * 8);
            }
        }
        #pragma unroll
        for (int i = 0; i < 2; i++) {
            int c = tid + i * 256, row = c >> 4, col = c & 15;
            cp16(Bres + row * 272 + col * 16, cpb + (size_t)row * 1024 + col * 8);
        }
        cpcommit();
    }

    for (int it = 0; it < 5; ++it) {
        const int buf = it & 1;
        if (it + 1 < 5) {
            const int k0 = (it + 1) * 32, nb = buf ^ 1;
            #pragma unroll
            for (int i = 0; i < 3; i++) {
                int c = tid + i * 256;
                if (c < 640) {
                    int row = c / 20, col = c % 20;
                    cp16(AB[nb] + row * 336 + col * 16,
                         Gp + (size_t)(k0 + row) * 160 + col * 8);
                }
            }
            #pragma unroll
            for (int i = 0; i < 2; i++) {
                int c = tid + i * 256, row = c >> 4, col = c & 15;
                cp16(Bres + (k0 + row) * 272 + col * 16,
                     cpb + (size_t)(k0 + row) * 1024 + col * 8);
            }
            cpcommit();
            cpwait1();
        } else {
            cpwait0();
        }
        __syncthreads();
        #pragma unroll
        for (int s = 0; s < 2; s++) {
            if (s == 1 && it == 4) break;   // G rows k'=144..159 are zero
            uint32_t a[5][4], bb[2][4];
            #pragma unroll
            for (int t = 0; t < 5; t++)
                ldsm4t(a[t], AB[buf] + (s * 16 + aK) * 336 + (Wm + t * 16 + aI) * 2);
            #pragma unroll
            for (int q = 0; q < 2; q++)
                ldsm4t(bb[q], Bres + (it * 32 + s * 16 + bK) * 272 + (Wn + q * 16 + bJ) * 2);
            #pragma unroll
            for (int mt = 0; mt < 5; mt++)
                #pragma unroll
                for (int nt = 0; nt < 4; nt++)
                    mma_f16(acc[mt][nt], a[mt], &bb[nt >> 1][(nt & 1) * 2]);
        }
        __syncthreads();
    }

    #pragma unroll
    for (int nt = 0; nt < 4; nt++) {
        #pragma unroll
        for (int cc = 0; cc < 2; cc++) {
            int gn = Wn + nt * 8 + 2 * (l & 3) + cc;
            float s = 0.f;
            #pragma unroll
            for (int mt = 0; mt < 5; mt++) {
                int gm1 = Wm + mt * 16 + (l >> 2);
                int gm2 = gm1 + 8;
                float a1 = __half2float(*(const __half*)(smraw + 21504 + gm1 * 272 + gn * 2));
                float a2 = __half2float(*(const __half*)(smraw + 21504 + gm2 * 272 + gn * 2));
                s += a1 * acc[mt][nt][cc] + a2 * acc[mt][nt][2 + cc];
            }
            atomicAdd(&S[gn], s);
        }
    }
    __syncthreads();
    if (tid < 128) {
        float nrm = sqrtf(S[tid]);
        g_scale[(size_t)pout * HS + i0 + tid] = 1.0f / fmaxf(nrm, 1e-12f);
    }
}

// ---------------- cofe GEMM: full-panel resident, occ 2, scaled epilogue ----
// smem: Apanel[160][272B] @0, Bpanel[160][272B] @43520 -> 87040 per CTA
#define COFE_SMEM 87040
__global__ void __launch_bounds__(128, 2) cofe_kernel(float* __restrict__ out) {
    extern __shared__ char smraw[];
    const uint32_t sb = smem_u32(smraw);
    const int tid = threadIdx.x, wid = tid >> 5, l = tid & 31;
    const int j0 = blockIdx.x * 128, i0 = blockIdx.y * 128;
    const int p = blockIdx.z, b = p / NO, o = p - b * NO;

    const __half* Ag = g_cp2 + (size_t)b * 160 * 1024 + i0;
    const __half* Bg = g_sp2 + (size_t)(o * BB + b) * 160 * 1024 + j0;

    const uint32_t Apan = sb;
    const uint32_t Bpan = sb + 43520;

    const int Wm = (wid >> 1) * 64, Wn = (wid & 1) * 64;
    const int aK = (l & 7) + (l >> 4) * 8, aI = ((l >> 3) & 1) * 8;
    const int bK = (l & 7) + ((l >> 3) & 1) * 8, bJ = (l >> 4) * 8;

    float acc[4][8][4] = {};

    // chunk 1: rows 0..63 of A and B
    #pragma unroll
    for (int i = 0; i < 8; i++) {
        int c = tid + i * 128, k = c >> 4, jc = c & 15;
        cp16(Apan + k * 272 + jc * 16, Ag + (size_t)k * 1024 + jc * 8);
    }
    #pragma unroll
    for (int i = 0; i < 8; i++) {
        int c = tid + i * 128, k = c >> 4, jc = c & 15;
        cp16(Bpan + k * 272 + jc * 16, Bg + (size_t)k * 1024 + jc * 8);
    }
    cpcommit();
    // chunk 2: rows 64..143 (80 rows; rows 144..159 never read)
    #pragma unroll
    for (int i = 0; i < 10; i++) {
        int c = tid + i * 128, k = 64 + (c >> 4), jc = c & 15;
        cp16(Apan + k * 272 + jc * 16, Ag + (size_t)k * 1024 + jc * 8);
    }
    #pragma unroll
    for (int i = 0; i < 10; i++) {
        int c = tid + i * 128, k = 64 + (c >> 4), jc = c & 15;
        cp16(Bpan + k * 272 + jc * 16, Bg + (size_t)k * 1024 + jc * 8);
    }
    cpcommit();

    cpwait1();
    __syncthreads();
    #pragma unroll
    for (int s = 0; s < 4; s++) {
        uint32_t a[4][4], bb[4][4];
        #pragma unroll
        for (int q = 0; q < 4; q++)
            ldsm4t(bb[q], Bpan + (s * 16 + bK) * 272 + (Wn + q * 16 + bJ) * 2);
        #pragma unroll
        for (int t = 0; t < 4; t++)
            ldsm4t(a[t], Apan + (s * 16 + aK) * 272 + (Wm + t * 16 + aI) * 2);
        #pragma unroll
        for (int mt = 0; mt < 4; mt++)
            #pragma unroll
            for (int nt = 0; nt < 8; nt++)
                mma_f16(acc[mt][nt], a[mt], &bb[nt >> 1][(nt & 1) * 2]);
    }
    cpwait0();
    __syncthreads();
    #pragma unroll
    for (int s = 4; s < 9; s++) {
        uint32_t a[4][4], bb[4][4];
        #pragma unroll
        for (int q = 0; q < 4; q++)
            ldsm4t(bb[q], Bpan + (s * 16 + bK) * 272 + (Wn + q * 16 + bJ) * 2);
        #pragma unroll
        for (int t = 0; t < 4; t++)
            ldsm4t(a[t], Apan + (s * 16 + aK) * 272 + (Wm + t * 16 + aI) * 2);
        #pragma unroll
        for (int mt = 0; mt < 4; mt++)
            #pragma unroll
            for (int nt = 0; nt < 8; nt++)
                mma_f16(acc[mt][nt], a[mt], &bb[nt >> 1][(nt & 1) * 2]);
    }

    float* outp = out + (size_t)p * HS * HS;
    const float* scl = g_scale + (size_t)p * HS + i0;
    #pragma unroll
    for (int mt = 0; mt < 4; mt++) {
        int lr = Wm + mt * 16 + (l >> 2);
        int gi = i0 + lr;
        float s1 = scl[lr], s2 = scl[lr + 8];
        #pragma unroll
        for (int nt = 0; nt < 8; nt++) {
            int gj = j0 + Wn + nt * 8 + 2 * (l & 3);
            *reinterpret_cast<float2*>(outp + (size_t)gi * HS + gj) =
                make_float2(acc[mt][nt][0] * s1, acc[mt][nt][1] * s1);
            *reinterpret_cast<float2*>(outp + (size_t)(gi + 8) * HS + gj) =
                make_float2(acc[mt][nt][2] * s2, acc[mt][nt][3] * s2);
        }
    }
}

// ---------------------------------------------------------------------------
extern "C" void kernel_launch(void* const* d_in, const int* in_sizes, int n_in,
                              void* d_out, int out_size) {
    const float* x  = (const float*)d_in[0];
    const float* w1 = (const float*)d_in[1];
    const float* b1 = (const float*)d_in[2];
    const float* w2 = (const float*)d_in[3];
    const float* b2 = (const float*)d_in[4];
    float* out = (float*)d_out;

    cudaFuncSetAttribute(proj_kernel, cudaFuncAttributeMaxDynamicSharedMemorySize, PROJ_SMEM);
    cudaFuncSetAttribute(gram_kernel, cudaFuncAttributeMaxDynamicSharedMemorySize, GRAM_SMEM);
    cudaFuncSetAttribute(tmat_kernel, cudaFuncAttributeMaxDynamicSharedMemorySize, TMAT_SMEM);
    cudaFuncSetAttribute(cofe_kernel, cudaFuncAttributeMaxDynamicSharedMemorySize, COFE_SMEM);

    conv_w2<<<dim3((HS * CC) / 256, 2), 256>>>(w1, w2);
    conv_x2<<<dim3(CC / 32, (HW + 31) / 32, BB), dim3(32, 8)>>>(x);
    proj_kernel<<<dim3(HS / 128, (10 * BB * KP) / 128), 256, PROJ_SMEM>>>(b1, b2);
    gram_kernel<<<2 * NO * BB, 256, GRAM_SMEM>>>();
    greduce_kernel<<<(NO * BB * 25600) / 256, 256>>>();
    tmat_kernel<<<dim3(HS / 128, NO * BB), 256, TMAT_SMEM>>>();
    cofe_kernel<<<dim3(HS / 128, HS / 128, BB * NO), 128, COFE_SMEM>>>(out);
}